// round 3
// baseline (speedup 1.0000x reference)
#include <cuda_runtime.h>

#define Bb 2
#define Ss 2048
#define Hh 1024
#define HEADS 16
#define KD 64
#define VD 2048
#define HD 128
#define MS (Bb*Ss)   /* 4096 rows */

// ---------------- scratch (device globals; no allocation allowed) ----------
__device__ float g_q [MS*Hh];
__device__ float g_k [MS*Hh];
__device__ float g_v [MS*VD];
__device__ float g_g [MS*VD];
__device__ float g_ao[MS*VD];

// ---------------- generic C = alpha * A(MxK) * B(NxK)^T  (both K-major) ----
__global__ __launch_bounds__(256, 2)
void gemm_nt(const float* __restrict__ A, const float* __restrict__ Bm,
             float* __restrict__ C, int M, int N, int K, float alpha)
{
    __shared__ float As[16][132];
    __shared__ float Bs[16][132];
    const int tid = threadIdx.x;
    const int tm  = tid >> 4;        // 0..15
    const int tn  = tid & 15;        // 0..15
    const int m0  = blockIdx.y * 128;
    const int n0  = blockIdx.x * 128;

    const int row = tid >> 2;        // 0..63
    const int c4  = (tid & 3) * 4;   // 0,4,8,12

    float acc[8][8];
#pragma unroll
    for (int i = 0; i < 8; i++)
#pragma unroll
        for (int j = 0; j < 8; j++) acc[i][j] = 0.f;

    // prefetch tile 0
    float4 ra0 = *(const float4*)&A [(size_t)(m0 + row     ) * K + c4];
    float4 ra1 = *(const float4*)&A [(size_t)(m0 + row + 64) * K + c4];
    float4 rb0 = *(const float4*)&Bm[(size_t)(n0 + row     ) * K + c4];
    float4 rb1 = *(const float4*)&Bm[(size_t)(n0 + row + 64) * K + c4];

    for (int k0 = 0; k0 < K; k0 += 16) {
        As[c4+0][row   ] = ra0.x; As[c4+1][row   ] = ra0.y;
        As[c4+2][row   ] = ra0.z; As[c4+3][row   ] = ra0.w;
        As[c4+0][row+64] = ra1.x; As[c4+1][row+64] = ra1.y;
        As[c4+2][row+64] = ra1.z; As[c4+3][row+64] = ra1.w;
        Bs[c4+0][row   ] = rb0.x; Bs[c4+1][row   ] = rb0.y;
        Bs[c4+2][row   ] = rb0.z; Bs[c4+3][row   ] = rb0.w;
        Bs[c4+0][row+64] = rb1.x; Bs[c4+1][row+64] = rb1.y;
        Bs[c4+2][row+64] = rb1.z; Bs[c4+3][row+64] = rb1.w;
        __syncthreads();

        if (k0 + 16 < K) {
            int kn = k0 + 16 + c4;
            ra0 = *(const float4*)&A [(size_t)(m0 + row     ) * K + kn];
            ra1 = *(const float4*)&A [(size_t)(m0 + row + 64) * K + kn];
            rb0 = *(const float4*)&Bm[(size_t)(n0 + row     ) * K + kn];
            rb1 = *(const float4*)&Bm[(size_t)(n0 + row + 64) * K + kn];
        }

#pragma unroll
        for (int kk = 0; kk < 16; kk++) {
            float4 a0 = *(const float4*)&As[kk][tm * 8];
            float4 a1 = *(const float4*)&As[kk][tm * 8 + 4];
            float4 b0 = *(const float4*)&Bs[kk][tn * 8];
            float4 b1 = *(const float4*)&Bs[kk][tn * 8 + 4];
            float av[8] = {a0.x, a0.y, a0.z, a0.w, a1.x, a1.y, a1.z, a1.w};
            float bv[8] = {b0.x, b0.y, b0.z, b0.w, b1.x, b1.y, b1.z, b1.w};
#pragma unroll
            for (int i = 0; i < 8; i++)
#pragma unroll
                for (int j = 0; j < 8; j++) acc[i][j] += av[i] * bv[j];
        }
        __syncthreads();
    }

#pragma unroll
    for (int i = 0; i < 8; i++) {
        float4 o0, o1;
        o0.x = alpha*acc[i][0]; o0.y = alpha*acc[i][1];
        o0.z = alpha*acc[i][2]; o0.w = alpha*acc[i][3];
        o1.x = alpha*acc[i][4]; o1.y = alpha*acc[i][5];
        o1.z = alpha*acc[i][6]; o1.w = alpha*acc[i][7];
        size_t off = (size_t)(m0 + tm * 8 + i) * N + n0 + tn * 8;
        *(float4*)&C[off]     = o0;
        *(float4*)&C[off + 4] = o1;
    }
}

// ---------------- rotary (theta-shift), in place on q and k ----------------
__global__ void rope_kernel(float* __restrict__ q, float* __restrict__ k,
                            const float* __restrict__ sn, const float* __restrict__ cs)
{
    int idx = blockIdx.x * blockDim.x + threadIdx.x;     // pair index
    if (idx >= MS * Hh / 2) return;
    int pir = idx % (Hh / 2);           // pair-in-row 0..511
    int row = idx / (Hh / 2);           // b*S + s
    int s   = row % Ss;
    int p   = pir % (KD / 2);           // pair within head
    int base = row * Hh + pir * 2;
    float c0 = cs[s * KD + 2 * p], c1 = cs[s * KD + 2 * p + 1];
    float s0 = sn[s * KD + 2 * p], s1 = sn[s * KD + 2 * p + 1];

    float2 qv = *(float2*)&q[base];
    float2 kv = *(float2*)&k[base];
    float2 qo, ko;
    qo.x = qv.x * c0 - qv.y * s0;
    qo.y = qv.y * c1 + qv.x * s1;
    ko.x = kv.x * c0 - kv.y * s0;
    ko.y = kv.y * c1 + kv.x * s1;
    *(float2*)&q[base] = qo;
    *(float2*)&k[base] = ko;
}

// ---------------- retention attention ---------------------------------------
// grid: (S/64, B*HEADS), 256 threads. Flash-style causal loop; divides by
// max(|rowsum|,1) once at the end (division is a per-row scalar -> identical).
#define SQ 68
__global__ __launch_bounds__(256, 2)
void attn_kernel(const float* __restrict__ q, const float* __restrict__ k,
                 const float* __restrict__ v, const float* __restrict__ mask,
                 float* __restrict__ ao)
{
    extern __shared__ float sm[];
    float* Qs  = sm;                 // [64][SQ]
    float* KsT = Qs  + 64 * SQ;      // [64(c)][SQ] transposed K
    float* Ssm = KsT + 64 * SQ;      // [64][SQ]
    float* Vs  = Ssm + 64 * SQ;      // [64][128]
    float* rowsum = Vs + 64 * 128;   // [64]

    const int tid = threadIdx.x;
    const int sb  = blockIdx.x;
    const int bh  = blockIdx.y;
    const int b   = bh / HEADS, h = bh % HEADS;
    const int s0  = sb * 64;
    const int ty  = tid >> 4, tx = tid & 15;

    if (tid < 64) rowsum[tid] = 0.f;

    // load Q tile (64x64) once
#pragma unroll
    for (int l = 0; l < 4; l++) {
        int lin = tid + l * 256;
        int r = lin >> 4, c4 = (lin & 15) << 2;
        float4 qv = *(const float4*)&q[(size_t)(b * Ss + s0 + r) * Hh + h * KD + c4];
        *(float4*)&Qs[r * SQ + c4] = qv;
    }

    float oacc[4][8];
#pragma unroll
    for (int r = 0; r < 4; r++)
#pragma unroll
        for (int j = 0; j < 8; j++) oacc[r][j] = 0.f;

    __syncthreads();

    for (int tt = 0; tt <= sb; tt++) {
        const int t0 = tt * 64;
        // K tile -> transposed smem
#pragma unroll
        for (int l = 0; l < 4; l++) {
            int lin = tid + l * 256;
            int j = lin >> 4, c4 = (lin & 15) << 2;
            float4 kv = *(const float4*)&k[(size_t)(b * Ss + t0 + j) * Hh + h * KD + c4];
            KsT[(c4 + 0) * SQ + j] = kv.x;
            KsT[(c4 + 1) * SQ + j] = kv.y;
            KsT[(c4 + 2) * SQ + j] = kv.z;
            KsT[(c4 + 3) * SQ + j] = kv.w;
        }
        // V tile (64x128)
#pragma unroll
        for (int l = 0; l < 8; l++) {
            int lin = tid + l * 256;
            int t = lin >> 5, c4 = (lin & 31) << 2;
            float4 vv = *(const float4*)&v[(size_t)(b * Ss + t0 + t) * VD + h * HD + c4];
            *(float4*)&Vs[t * 128 + c4] = vv;
        }
        __syncthreads();

        // ---- S = Q * K^T (64x64), thread -> 4x4 micro-tile -----------------
        float sacc[4][4];
#pragma unroll
        for (int r = 0; r < 4; r++)
#pragma unroll
            for (int j = 0; j < 4; j++) sacc[r][j] = 0.f;

#pragma unroll 8
        for (int c = 0; c < 64; c++) {
            float4 bv = *(const float4*)&KsT[c * SQ + tx * 4];
#pragma unroll
            for (int r = 0; r < 4; r++) {
                float a = Qs[(ty * 4 + r) * SQ + c];
                sacc[r][0] += a * bv.x;
                sacc[r][1] += a * bv.y;
                sacc[r][2] += a * bv.z;
                sacc[r][3] += a * bv.w;
            }
        }

        // ---- mask, rowsum, stash S ----------------------------------------
        float part[4];
#pragma unroll
        for (int r = 0; r < 4; r++) {
            int i = ty * 4 + r;
            float4 mv = *(const float4*)&mask[(size_t)h * Ss * Ss +
                                              (size_t)(s0 + i) * Ss + t0 + tx * 4];
            float4 sv;
            sv.x = sacc[r][0] * mv.x;
            sv.y = sacc[r][1] * mv.y;
            sv.z = sacc[r][2] * mv.z;
            sv.w = sacc[r][3] * mv.w;
            part[r] = sv.x + sv.y + sv.z + sv.w;
            *(float4*)&Ssm[i * SQ + tx * 4] = sv;
        }
#pragma unroll
        for (int r = 0; r < 4; r++) {
#pragma unroll
            for (int o = 8; o > 0; o >>= 1)
                part[r] += __shfl_xor_sync(0xffffffffu, part[r], o);
            if (tx == 0) rowsum[ty * 4 + r] += part[r];
        }
        __syncthreads();

        // ---- O += S * V (64x128), thread -> 4 rows x 8 cols ---------------
#pragma unroll 8
        for (int t = 0; t < 64; t++) {
            float4 b0 = *(const float4*)&Vs[t * 128 + tx * 8];
            float4 b1 = *(const float4*)&Vs[t * 128 + tx * 8 + 4];
#pragma unroll
            for (int r = 0; r < 4; r++) {
                float a = Ssm[(ty * 4 + r) * SQ + t];
                oacc[r][0] += a * b0.x; oacc[r][1] += a * b0.y;
                oacc[r][2] += a * b0.z; oacc[r][3] += a * b0.w;
                oacc[r][4] += a * b1.x; oacc[r][5] += a * b1.y;
                oacc[r][6] += a * b1.z; oacc[r][7] += a * b1.w;
            }
        }
        __syncthreads();
    }

    // ---- normalize by max(|rowsum|,1) and write ---------------------------
#pragma unroll
    for (int r = 0; r < 4; r++) {
        int i = ty * 4 + r;
        float inv = 1.f / fmaxf(fabsf(rowsum[i]), 1.f);
        float4 o0, o1;
        o0.x = oacc[r][0]*inv; o0.y = oacc[r][1]*inv;
        o0.z = oacc[r][2]*inv; o0.w = oacc[r][3]*inv;
        o1.x = oacc[r][4]*inv; o1.y = oacc[r][5]*inv;
        o1.z = oacc[r][6]*inv; o1.w = oacc[r][7]*inv;
        size_t off = (size_t)(b * Ss + s0 + i) * VD + h * HD + tx * 8;
        *(float4*)&ao[off]     = o0;
        *(float4*)&ao[off + 4] = o1;
    }
}

// ---------------- group RMS-norm (per head, 128 dims) + SiLU gate ----------
__global__ void gnorm_gate(float* __restrict__ ao, const float* __restrict__ g)
{
    int gid  = (blockIdx.x * blockDim.x + threadIdx.x) >> 5;   // group = warp
    int lane = threadIdx.x & 31;
    if (gid >= MS * HEADS) return;
    int row = gid / HEADS;
    int hh  = gid % HEADS;
    size_t base = (size_t)row * VD + hh * HD + lane * 4;

    float4 x = *(const float4*)&ao[base];
    float ss = x.x*x.x + x.y*x.y + x.z*x.z + x.w*x.w;
#pragma unroll
    for (int o = 16; o > 0; o >>= 1) ss += __shfl_xor_sync(0xffffffffu, ss, o);
    float r = rsqrtf(ss * (1.f / 128.f) + 1e-5f);

    float4 gv = *(const float4*)&g[base];
    float4 o;
    o.x = x.x * r * gv.x * (1.f / (1.f + __expf(-gv.x)));
    o.y = x.y * r * gv.y * (1.f / (1.f + __expf(-gv.y)));
    o.z = x.z * r * gv.z * (1.f / (1.f + __expf(-gv.z)));
    o.w = x.w * r * gv.w * (1.f / (1.f + __expf(-gv.w)));
    *(float4*)&ao[base] = o;
}

// ---------------- launcher -------------------------------------------------
extern "C" void kernel_launch(void* const* d_in, const int* in_sizes, int n_in,
                              void* d_out, int out_size)
{
    const float* x    = (const float*)d_in[0];
    const float* sn   = (const float*)d_in[1];
    const float* cs   = (const float*)d_in[2];
    const float* mask = (const float*)d_in[3];
    const float* Wq   = (const float*)d_in[4];
    const float* Wk   = (const float*)d_in[5];
    const float* Wv   = (const float*)d_in[6];
    const float* Wg   = (const float*)d_in[7];
    const float* Wo   = (const float*)d_in[8];
    float* out = (float*)d_out;

    float *q, *k, *v, *g, *ao;
    cudaGetSymbolAddress((void**)&q,  g_q);
    cudaGetSymbolAddress((void**)&k,  g_k);
    cudaGetSymbolAddress((void**)&v,  g_v);
    cudaGetSymbolAddress((void**)&g,  g_g);
    cudaGetSymbolAddress((void**)&ao, g_ao);

    const int attn_smem = (3 * 64 * SQ + 64 * 128 + 64) * (int)sizeof(float);
    cudaFuncSetAttribute(attn_kernel, cudaFuncAttributeMaxDynamicSharedMemorySize,
                         attn_smem);

    dim3 gN1(Hh / 128, MS / 128);   // (8, 32)
    dim3 gN2(VD / 128, MS / 128);   // (16, 32)

    gemm_nt<<<gN1, 256>>>(x, Wq, q, MS, Hh, Hh, 1.0f);
    gemm_nt<<<gN1, 256>>>(x, Wk, k, MS, Hh, Hh, 0.125f);   // kd^-0.5 = 1/8
    gemm_nt<<<gN2, 256>>>(x, Wv, v, MS, VD, Hh, 1.0f);
    gemm_nt<<<gN2, 256>>>(x, Wg, g, MS, VD, Hh, 1.0f);

    rope_kernel<<<(MS * Hh / 2 + 255) / 256, 256>>>(q, k, sn, cs);

    attn_kernel<<<dim3(Ss / 64, Bb * HEADS), 256, attn_smem>>>(q, k, v, mask, ao);

    gnorm_gate<<<(MS * HEADS * 32 + 255) / 256, 256>>>(ao, g);

    gemm_nt<<<dim3(Hh / 128, MS / 128), 256>>>(ao, Wo, out, MS, Hh, VD, 1.0f);
}

// round 4
// speedup vs baseline: 1.4320x; 1.4320x over previous
#include <cuda_runtime.h>

#define Bb 2
#define Ss 2048
#define Hh 1024
#define HEADS 16
#define KD 64
#define VD 2048
#define HD 128
#define MS (Bb*Ss)   /* 4096 rows */

// ---------------- scratch (device globals; no allocation allowed) ----------
__device__ float g_q [MS*Hh];
__device__ float g_k [MS*Hh];
__device__ float g_v [MS*VD];
__device__ float g_g [MS*VD];
__device__ float g_ao[MS*VD];

// ---------------- helpers --------------------------------------------------
__device__ __forceinline__ float to_tf32(float x) {
    unsigned u;
    asm("cvt.rna.tf32.f32 %0, %1;" : "=r"(u) : "f"(x));
    return __uint_as_float(u);
}

#define MMA_TF32(c, a, b)                                                     \
    asm volatile(                                                             \
        "mma.sync.aligned.m16n8k8.row.col.f32.tf32.tf32.f32 "                 \
        "{%0,%1,%2,%3}, {%4,%5,%6,%7}, {%8,%9}, {%0,%1,%2,%3};"               \
        : "+f"((c)[0]), "+f"((c)[1]), "+f"((c)[2]), "+f"((c)[3])              \
        : "r"((a)[0]), "r"((a)[1]), "r"((a)[2]), "r"((a)[3]),                 \
          "r"((b)[0]), "r"((b)[1]))

// ---------------- tensor-core C = alpha * A(MxK) * B(NxK)^T ----------------
// Block: 128x128 tile, 256 thr (8 warps, 2x4), warp tile 64x32, tf32 MMA.
#define SAstr 136   /* k-major smem stride: 136 mod 32 = 8 -> conflict-free frags */
__global__ __launch_bounds__(256, 2)
void gemm_nt_tc(const float* __restrict__ A, const float* __restrict__ Bm,
                float* __restrict__ C, int M, int N, int K, float alpha)
{
    __shared__ float As[16 * SAstr];
    __shared__ float Bs[16 * SAstr];

    const int tid    = threadIdx.x;
    const int warp   = tid >> 5;
    const int lane   = tid & 31;
    const int g      = lane >> 2;     // groupID 0..7
    const int t      = lane & 3;      // thread-in-group 0..3
    const int warp_m = warp >> 2;     // 0..1  (64 rows each)
    const int warp_n = warp & 3;      // 0..3  (32 cols each)
    const int m0     = blockIdx.y * 128;
    const int n0     = blockIdx.x * 128;

    // cooperative load mapping (same as proven fp32 kernel)
    const int row = tid >> 2;         // 0..63
    const int c4  = (tid & 3) * 4;    // 0,4,8,12

    float acc[4][4][4];
#pragma unroll
    for (int i = 0; i < 4; i++)
#pragma unroll
        for (int j = 0; j < 4; j++)
#pragma unroll
            for (int r = 0; r < 4; r++) acc[i][j][r] = 0.f;

    // prefetch tile 0
    float4 ra0 = *(const float4*)&A [(size_t)(m0 + row     ) * K + c4];
    float4 ra1 = *(const float4*)&A [(size_t)(m0 + row + 64) * K + c4];
    float4 rb0 = *(const float4*)&Bm[(size_t)(n0 + row     ) * K + c4];
    float4 rb1 = *(const float4*)&Bm[(size_t)(n0 + row + 64) * K + c4];

    for (int k0 = 0; k0 < K; k0 += 16) {
        // store (tf32-rounded) into k-major smem: s[k][m]
        As[(c4+0)*SAstr + row   ] = to_tf32(ra0.x);
        As[(c4+1)*SAstr + row   ] = to_tf32(ra0.y);
        As[(c4+2)*SAstr + row   ] = to_tf32(ra0.z);
        As[(c4+3)*SAstr + row   ] = to_tf32(ra0.w);
        As[(c4+0)*SAstr + row+64] = to_tf32(ra1.x);
        As[(c4+1)*SAstr + row+64] = to_tf32(ra1.y);
        As[(c4+2)*SAstr + row+64] = to_tf32(ra1.z);
        As[(c4+3)*SAstr + row+64] = to_tf32(ra1.w);
        Bs[(c4+0)*SAstr + row   ] = to_tf32(rb0.x);
        Bs[(c4+1)*SAstr + row   ] = to_tf32(rb0.y);
        Bs[(c4+2)*SAstr + row   ] = to_tf32(rb0.z);
        Bs[(c4+3)*SAstr + row   ] = to_tf32(rb0.w);
        Bs[(c4+0)*SAstr + row+64] = to_tf32(rb1.x);
        Bs[(c4+1)*SAstr + row+64] = to_tf32(rb1.y);
        Bs[(c4+2)*SAstr + row+64] = to_tf32(rb1.z);
        Bs[(c4+3)*SAstr + row+64] = to_tf32(rb1.w);
        __syncthreads();

        if (k0 + 16 < K) {
            int kn = k0 + 16 + c4;
            ra0 = *(const float4*)&A [(size_t)(m0 + row     ) * K + kn];
            ra1 = *(const float4*)&A [(size_t)(m0 + row + 64) * K + kn];
            rb0 = *(const float4*)&Bm[(size_t)(n0 + row     ) * K + kn];
            rb1 = *(const float4*)&Bm[(size_t)(n0 + row + 64) * K + kn];
        }

#pragma unroll
        for (int ks = 0; ks < 2; ks++) {
            const int kb = ks * 8;
            unsigned af[4][4];
#pragma unroll
            for (int mi = 0; mi < 4; mi++) {
                int mb = warp_m * 64 + mi * 16 + g;
                af[mi][0] = __float_as_uint(As[(kb + t    ) * SAstr + mb    ]);
                af[mi][1] = __float_as_uint(As[(kb + t    ) * SAstr + mb + 8]);
                af[mi][2] = __float_as_uint(As[(kb + t + 4) * SAstr + mb    ]);
                af[mi][3] = __float_as_uint(As[(kb + t + 4) * SAstr + mb + 8]);
            }
            unsigned bf[4][2];
#pragma unroll
            for (int nj = 0; nj < 4; nj++) {
                int nb = warp_n * 32 + nj * 8 + g;
                bf[nj][0] = __float_as_uint(Bs[(kb + t    ) * SAstr + nb]);
                bf[nj][1] = __float_as_uint(Bs[(kb + t + 4) * SAstr + nb]);
            }
#pragma unroll
            for (int mi = 0; mi < 4; mi++)
#pragma unroll
                for (int nj = 0; nj < 4; nj++)
                    MMA_TF32(acc[mi][nj], af[mi], bf[nj]);
        }
        __syncthreads();
    }

    // epilogue: c0:(g,2t) c1:(g,2t+1) c2:(g+8,2t) c3:(g+8,2t+1)
#pragma unroll
    for (int mi = 0; mi < 4; mi++) {
        int r0 = m0 + warp_m * 64 + mi * 16 + g;
#pragma unroll
        for (int nj = 0; nj < 4; nj++) {
            int col = n0 + warp_n * 32 + nj * 8 + 2 * t;
            float2 v01, v23;
            v01.x = alpha * acc[mi][nj][0];
            v01.y = alpha * acc[mi][nj][1];
            v23.x = alpha * acc[mi][nj][2];
            v23.y = alpha * acc[mi][nj][3];
            *(float2*)&C[(size_t)r0 * N + col]       = v01;
            *(float2*)&C[(size_t)(r0 + 8) * N + col] = v23;
        }
    }
}

// ---------------- rotary (theta-shift), in place on q and k ----------------
__global__ void rope_kernel(float* __restrict__ q, float* __restrict__ k,
                            const float* __restrict__ sn, const float* __restrict__ cs)
{
    int idx = blockIdx.x * blockDim.x + threadIdx.x;     // pair index
    if (idx >= MS * Hh / 2) return;
    int pir = idx % (Hh / 2);           // pair-in-row 0..511
    int row = idx / (Hh / 2);           // b*S + s
    int s   = row % Ss;
    int p   = pir % (KD / 2);           // pair within head
    int base = row * Hh + pir * 2;
    float c0 = cs[s * KD + 2 * p], c1 = cs[s * KD + 2 * p + 1];
    float s0 = sn[s * KD + 2 * p], s1 = sn[s * KD + 2 * p + 1];

    float2 qv = *(float2*)&q[base];
    float2 kv = *(float2*)&k[base];
    float2 qo, ko;
    qo.x = qv.x * c0 - qv.y * s0;
    qo.y = qv.y * c1 + qv.x * s1;
    ko.x = kv.x * c0 - kv.y * s0;
    ko.y = kv.y * c1 + kv.x * s1;
    *(float2*)&q[base] = qo;
    *(float2*)&k[base] = ko;
}

// ---------------- retention attention ---------------------------------------
// grid: (S/64, B*HEADS), 256 threads. Flash-style causal loop; divides by
// max(|rowsum|,1) once at the end (division is a per-row scalar -> identical).
#define SQ 68
__global__ __launch_bounds__(256, 2)
void attn_kernel(const float* __restrict__ q, const float* __restrict__ k,
                 const float* __restrict__ v, const float* __restrict__ mask,
                 float* __restrict__ ao)
{
    extern __shared__ float sm[];
    float* Qs  = sm;                 // [64][SQ]
    float* KsT = Qs  + 64 * SQ;      // [64(c)][SQ] transposed K
    float* Ssm = KsT + 64 * SQ;      // [64][SQ]
    float* Vs  = Ssm + 64 * SQ;      // [64][128]
    float* rowsum = Vs + 64 * 128;   // [64]

    const int tid = threadIdx.x;
    const int sb  = blockIdx.x;
    const int bh  = blockIdx.y;
    const int b   = bh / HEADS, h = bh % HEADS;
    const int s0  = sb * 64;
    const int ty  = tid >> 4, tx = tid & 15;

    if (tid < 64) rowsum[tid] = 0.f;

    // load Q tile (64x64) once
#pragma unroll
    for (int l = 0; l < 4; l++) {
        int lin = tid + l * 256;
        int r = lin >> 4, c4 = (lin & 15) << 2;
        float4 qv = *(const float4*)&q[(size_t)(b * Ss + s0 + r) * Hh + h * KD + c4];
        *(float4*)&Qs[r * SQ + c4] = qv;
    }

    float oacc[4][8];
#pragma unroll
    for (int r = 0; r < 4; r++)
#pragma unroll
        for (int j = 0; j < 8; j++) oacc[r][j] = 0.f;

    __syncthreads();

    for (int tt = 0; tt <= sb; tt++) {
        const int t0 = tt * 64;
        // K tile -> transposed smem
#pragma unroll
        for (int l = 0; l < 4; l++) {
            int lin = tid + l * 256;
            int j = lin >> 4, c4 = (lin & 15) << 2;
            float4 kv = *(const float4*)&k[(size_t)(b * Ss + t0 + j) * Hh + h * KD + c4];
            KsT[(c4 + 0) * SQ + j] = kv.x;
            KsT[(c4 + 1) * SQ + j] = kv.y;
            KsT[(c4 + 2) * SQ + j] = kv.z;
            KsT[(c4 + 3) * SQ + j] = kv.w;
        }
        // V tile (64x128)
#pragma unroll
        for (int l = 0; l < 8; l++) {
            int lin = tid + l * 256;
            int t = lin >> 5, c4 = (lin & 31) << 2;
            float4 vv = *(const float4*)&v[(size_t)(b * Ss + t0 + t) * VD + h * HD + c4];
            *(float4*)&Vs[t * 128 + c4] = vv;
        }
        __syncthreads();

        // ---- S = Q * K^T (64x64), thread -> 4x4 micro-tile -----------------
        float sacc[4][4];
#pragma unroll
        for (int r = 0; r < 4; r++)
#pragma unroll
            for (int j = 0; j < 4; j++) sacc[r][j] = 0.f;

#pragma unroll 8
        for (int c = 0; c < 64; c++) {
            float4 bv = *(const float4*)&KsT[c * SQ + tx * 4];
#pragma unroll
            for (int r = 0; r < 4; r++) {
                float a = Qs[(ty * 4 + r) * SQ + c];
                sacc[r][0] += a * bv.x;
                sacc[r][1] += a * bv.y;
                sacc[r][2] += a * bv.z;
                sacc[r][3] += a * bv.w;
            }
        }

        // ---- mask, rowsum, stash S ----------------------------------------
        float part[4];
#pragma unroll
        for (int r = 0; r < 4; r++) {
            int i = ty * 4 + r;
            float4 mv = *(const float4*)&mask[(size_t)h * Ss * Ss +
                                              (size_t)(s0 + i) * Ss + t0 + tx * 4];
            float4 sv;
            sv.x = sacc[r][0] * mv.x;
            sv.y = sacc[r][1] * mv.y;
            sv.z = sacc[r][2] * mv.z;
            sv.w = sacc[r][3] * mv.w;
            part[r] = sv.x + sv.y + sv.z + sv.w;
            *(float4*)&Ssm[i * SQ + tx * 4] = sv;
        }
#pragma unroll
        for (int r = 0; r < 4; r++) {
#pragma unroll
            for (int o = 8; o > 0; o >>= 1)
                part[r] += __shfl_xor_sync(0xffffffffu, part[r], o);
            if (tx == 0) rowsum[ty * 4 + r] += part[r];
        }
        __syncthreads();

        // ---- O += S * V (64x128), thread -> 4 rows x 8 cols ---------------
#pragma unroll 8
        for (int t = 0; t < 64; t++) {
            float4 b0 = *(const float4*)&Vs[t * 128 + tx * 8];
            float4 b1 = *(const float4*)&Vs[t * 128 + tx * 8 + 4];
#pragma unroll
            for (int r = 0; r < 4; r++) {
                float a = Ssm[(ty * 4 + r) * SQ + t];
                oacc[r][0] += a * b0.x; oacc[r][1] += a * b0.y;
                oacc[r][2] += a * b0.z; oacc[r][3] += a * b0.w;
                oacc[r][4] += a * b1.x; oacc[r][5] += a * b1.y;
                oacc[r][6] += a * b1.z; oacc[r][7] += a * b1.w;
            }
        }
        __syncthreads();
    }

    // ---- normalize by max(|rowsum|,1) and write ---------------------------
#pragma unroll
    for (int r = 0; r < 4; r++) {
        int i = ty * 4 + r;
        float inv = 1.f / fmaxf(fabsf(rowsum[i]), 1.f);
        float4 o0, o1;
        o0.x = oacc[r][0]*inv; o0.y = oacc[r][1]*inv;
        o0.z = oacc[r][2]*inv; o0.w = oacc[r][3]*inv;
        o1.x = oacc[r][4]*inv; o1.y = oacc[r][5]*inv;
        o1.z = oacc[r][6]*inv; o1.w = oacc[r][7]*inv;
        size_t off = (size_t)(b * Ss + s0 + i) * VD + h * HD + tx * 8;
        *(float4*)&ao[off]     = o0;
        *(float4*)&ao[off + 4] = o1;
    }
}

// ---------------- group RMS-norm (per head, 128 dims) + SiLU gate ----------
__global__ void gnorm_gate(float* __restrict__ ao, const float* __restrict__ g)
{
    int gid  = (blockIdx.x * blockDim.x + threadIdx.x) >> 5;   // group = warp
    int lane = threadIdx.x & 31;
    if (gid >= MS * HEADS) return;
    int row = gid / HEADS;
    int hh  = gid % HEADS;
    size_t base = (size_t)row * VD + hh * HD + lane * 4;

    float4 x = *(const float4*)&ao[base];
    float ss = x.x*x.x + x.y*x.y + x.z*x.z + x.w*x.w;
#pragma unroll
    for (int o = 16; o > 0; o >>= 1) ss += __shfl_xor_sync(0xffffffffu, ss, o);
    float r = rsqrtf(ss * (1.f / 128.f) + 1e-5f);

    float4 gv = *(const float4*)&g[base];
    float4 o;
    o.x = x.x * r * gv.x * (1.f / (1.f + __expf(-gv.x)));
    o.y = x.y * r * gv.y * (1.f / (1.f + __expf(-gv.y)));
    o.z = x.z * r * gv.z * (1.f / (1.f + __expf(-gv.z)));
    o.w = x.w * r * gv.w * (1.f / (1.f + __expf(-gv.w)));
    *(float4*)&ao[base] = o;
}

// ---------------- launcher -------------------------------------------------
extern "C" void kernel_launch(void* const* d_in, const int* in_sizes, int n_in,
                              void* d_out, int out_size)
{
    const float* x    = (const float*)d_in[0];
    const float* sn   = (const float*)d_in[1];
    const float* cs   = (const float*)d_in[2];
    const float* mask = (const float*)d_in[3];
    const float* Wq   = (const float*)d_in[4];
    const float* Wk   = (const float*)d_in[5];
    const float* Wv   = (const float*)d_in[6];
    const float* Wg   = (const float*)d_in[7];
    const float* Wo   = (const float*)d_in[8];
    float* out = (float*)d_out;

    float *q, *k, *v, *g, *ao;
    cudaGetSymbolAddress((void**)&q,  g_q);
    cudaGetSymbolAddress((void**)&k,  g_k);
    cudaGetSymbolAddress((void**)&v,  g_v);
    cudaGetSymbolAddress((void**)&g,  g_g);
    cudaGetSymbolAddress((void**)&ao, g_ao);

    const int attn_smem = (3 * 64 * SQ + 64 * 128 + 64) * (int)sizeof(float);
    cudaFuncSetAttribute(attn_kernel, cudaFuncAttributeMaxDynamicSharedMemorySize,
                         attn_smem);

    dim3 gN1(Hh / 128, MS / 128);   // (8, 32)
    dim3 gN2(VD / 128, MS / 128);   // (16, 32)

    gemm_nt_tc<<<gN1, 256>>>(x, Wq, q, MS, Hh, Hh, 1.0f);
    gemm_nt_tc<<<gN1, 256>>>(x, Wk, k, MS, Hh, Hh, 0.125f);   // kd^-0.5 = 1/8
    gemm_nt_tc<<<gN2, 256>>>(x, Wv, v, MS, VD, Hh, 1.0f);
    gemm_nt_tc<<<gN2, 256>>>(x, Wg, g, MS, VD, Hh, 1.0f);

    rope_kernel<<<(MS * Hh / 2 + 255) / 256, 256>>>(q, k, sn, cs);

    attn_kernel<<<dim3(Ss / 64, Bb * HEADS), 256, attn_smem>>>(q, k, v, mask, ao);

    gnorm_gate<<<(MS * HEADS * 32 + 255) / 256, 256>>>(ao, g);

    gemm_nt_tc<<<dim3(Hh / 128, MS / 128), 256>>>(ao, Wo, out, MS, Hh, VD, 1.0f);
}

// round 5
// speedup vs baseline: 2.3180x; 1.6187x over previous
#include <cuda_runtime.h>

#define Bb 2
#define Ss 2048
#define Hh 1024
#define HEADS 16
#define KD 64
#define VD 2048
#define HD 128
#define MS (Bb*Ss)   /* 4096 rows */

// ---------------- scratch (device globals; no allocation allowed) ----------
__device__ float g_q [MS*Hh];
__device__ float g_k [MS*Hh];
__device__ float g_v [MS*VD];
__device__ float g_g [MS*VD];
__device__ float g_ao[MS*VD];

// ---------------- helpers --------------------------------------------------
__device__ __forceinline__ float to_tf32(float x) {
    unsigned u;
    asm("cvt.rna.tf32.f32 %0, %1;" : "=r"(u) : "f"(x));
    return __uint_as_float(u);
}

#define MMA_TF32(c, a, b)                                                     \
    asm volatile(                                                             \
        "mma.sync.aligned.m16n8k8.row.col.f32.tf32.tf32.f32 "                 \
        "{%0,%1,%2,%3}, {%4,%5,%6,%7}, {%8,%9}, {%0,%1,%2,%3};"               \
        : "+f"((c)[0]), "+f"((c)[1]), "+f"((c)[2]), "+f"((c)[3])              \
        : "r"((a)[0]), "r"((a)[1]), "r"((a)[2]), "r"((a)[3]),                 \
          "r"((b)[0]), "r"((b)[1]))

// ---------------- tensor-core C = alpha * A(MxK) * B(NxK)^T ----------------
// Block: 128x128 tile, 256 thr (8 warps, 2x4), warp tile 64x32, tf32 MMA.
#define SAstr 136   /* k-major smem stride: 136 mod 32 = 8 -> conflict-free frags */
__global__ __launch_bounds__(256, 2)
void gemm_nt_tc(const float* __restrict__ A, const float* __restrict__ Bm,
                float* __restrict__ C, int M, int N, int K, float alpha)
{
    __shared__ float As[16 * SAstr];
    __shared__ float Bs[16 * SAstr];

    const int tid    = threadIdx.x;
    const int warp   = tid >> 5;
    const int lane   = tid & 31;
    const int g      = lane >> 2;     // groupID 0..7
    const int t      = lane & 3;      // thread-in-group 0..3
    const int warp_m = warp >> 2;     // 0..1  (64 rows each)
    const int warp_n = warp & 3;      // 0..3  (32 cols each)
    const int m0     = blockIdx.y * 128;
    const int n0     = blockIdx.x * 128;

    const int row = tid >> 2;         // 0..63
    const int c4  = (tid & 3) * 4;    // 0,4,8,12

    float acc[4][4][4];
#pragma unroll
    for (int i = 0; i < 4; i++)
#pragma unroll
        for (int j = 0; j < 4; j++)
#pragma unroll
            for (int r = 0; r < 4; r++) acc[i][j][r] = 0.f;

    float4 ra0 = *(const float4*)&A [(size_t)(m0 + row     ) * K + c4];
    float4 ra1 = *(const float4*)&A [(size_t)(m0 + row + 64) * K + c4];
    float4 rb0 = *(const float4*)&Bm[(size_t)(n0 + row     ) * K + c4];
    float4 rb1 = *(const float4*)&Bm[(size_t)(n0 + row + 64) * K + c4];

    for (int k0 = 0; k0 < K; k0 += 16) {
        As[(c4+0)*SAstr + row   ] = to_tf32(ra0.x);
        As[(c4+1)*SAstr + row   ] = to_tf32(ra0.y);
        As[(c4+2)*SAstr + row   ] = to_tf32(ra0.z);
        As[(c4+3)*SAstr + row   ] = to_tf32(ra0.w);
        As[(c4+0)*SAstr + row+64] = to_tf32(ra1.x);
        As[(c4+1)*SAstr + row+64] = to_tf32(ra1.y);
        As[(c4+2)*SAstr + row+64] = to_tf32(ra1.z);
        As[(c4+3)*SAstr + row+64] = to_tf32(ra1.w);
        Bs[(c4+0)*SAstr + row   ] = to_tf32(rb0.x);
        Bs[(c4+1)*SAstr + row   ] = to_tf32(rb0.y);
        Bs[(c4+2)*SAstr + row   ] = to_tf32(rb0.z);
        Bs[(c4+3)*SAstr + row   ] = to_tf32(rb0.w);
        Bs[(c4+0)*SAstr + row+64] = to_tf32(rb1.x);
        Bs[(c4+1)*SAstr + row+64] = to_tf32(rb1.y);
        Bs[(c4+2)*SAstr + row+64] = to_tf32(rb1.z);
        Bs[(c4+3)*SAstr + row+64] = to_tf32(rb1.w);
        __syncthreads();

        if (k0 + 16 < K) {
            int kn = k0 + 16 + c4;
            ra0 = *(const float4*)&A [(size_t)(m0 + row     ) * K + kn];
            ra1 = *(const float4*)&A [(size_t)(m0 + row + 64) * K + kn];
            rb0 = *(const float4*)&Bm[(size_t)(n0 + row     ) * K + kn];
            rb1 = *(const float4*)&Bm[(size_t)(n0 + row + 64) * K + kn];
        }

#pragma unroll
        for (int ks = 0; ks < 2; ks++) {
            const int kb = ks * 8;
            unsigned af[4][4];
#pragma unroll
            for (int mi = 0; mi < 4; mi++) {
                int mb = warp_m * 64 + mi * 16 + g;
                af[mi][0] = __float_as_uint(As[(kb + t    ) * SAstr + mb    ]);
                af[mi][1] = __float_as_uint(As[(kb + t    ) * SAstr + mb + 8]);
                af[mi][2] = __float_as_uint(As[(kb + t + 4) * SAstr + mb    ]);
                af[mi][3] = __float_as_uint(As[(kb + t + 4) * SAstr + mb + 8]);
            }
            unsigned bf[4][2];
#pragma unroll
            for (int nj = 0; nj < 4; nj++) {
                int nb = warp_n * 32 + nj * 8 + g;
                bf[nj][0] = __float_as_uint(Bs[(kb + t    ) * SAstr + nb]);
                bf[nj][1] = __float_as_uint(Bs[(kb + t + 4) * SAstr + nb]);
            }
#pragma unroll
            for (int mi = 0; mi < 4; mi++)
#pragma unroll
                for (int nj = 0; nj < 4; nj++)
                    MMA_TF32(acc[mi][nj], af[mi], bf[nj]);
        }
        __syncthreads();
    }

#pragma unroll
    for (int mi = 0; mi < 4; mi++) {
        int r0 = m0 + warp_m * 64 + mi * 16 + g;
#pragma unroll
        for (int nj = 0; nj < 4; nj++) {
            int col = n0 + warp_n * 32 + nj * 8 + 2 * t;
            float2 v01, v23;
            v01.x = alpha * acc[mi][nj][0];
            v01.y = alpha * acc[mi][nj][1];
            v23.x = alpha * acc[mi][nj][2];
            v23.y = alpha * acc[mi][nj][3];
            *(float2*)&C[(size_t)r0 * N + col]       = v01;
            *(float2*)&C[(size_t)(r0 + 8) * N + col] = v23;
        }
    }
}

// ---------------- rotary (theta-shift), in place on q and k ----------------
__global__ void rope_kernel(float* __restrict__ q, float* __restrict__ k,
                            const float* __restrict__ sn, const float* __restrict__ cs)
{
    int idx = blockIdx.x * blockDim.x + threadIdx.x;     // pair index
    if (idx >= MS * Hh / 2) return;
    int pir = idx % (Hh / 2);
    int row = idx / (Hh / 2);
    int s   = row % Ss;
    int p   = pir % (KD / 2);
    int base = row * Hh + pir * 2;
    float c0 = cs[s * KD + 2 * p], c1 = cs[s * KD + 2 * p + 1];
    float s0 = sn[s * KD + 2 * p], s1 = sn[s * KD + 2 * p + 1];

    float2 qv = *(float2*)&q[base];
    float2 kv = *(float2*)&k[base];
    float2 qo, ko;
    qo.x = qv.x * c0 - qv.y * s0;
    qo.y = qv.y * c1 + qv.x * s1;
    ko.x = kv.x * c0 - kv.y * s0;
    ko.y = kv.y * c1 + kv.x * s1;
    *(float2*)&q[base] = qo;
    *(float2*)&k[base] = ko;
}

// ---------------- retention attention (tf32 tensor-core) --------------------
// grid: (S/64, B*HEADS), 256 thr (8 warps). Per t-tile:
//   S = Q*K^T (MMA) -> mask in regs -> rowsum (shfl + deterministic smem
//   reduce) -> S (tf32) to smem -> O += S*V (MMA). Divide by max(|rowsum|,1)
//   once at the end. All fragment LDS conflict-free by stride choice:
//   Q/K/S stride 68 (bank=4g+t), V stride 136 (bank=8t+g).
#define AST 68
#define VST 136
__global__ __launch_bounds__(256, 2)
void attn_tc(const float* __restrict__ q, const float* __restrict__ k,
             const float* __restrict__ v, const float* __restrict__ mask,
             float* __restrict__ ao)
{
    extern __shared__ float sm[];
    float* Qs   = sm;                    // [64][AST]
    float* Ks   = Qs  + 64 * AST;        // [64][AST]
    float* Ssm  = Ks  + 64 * AST;        // [64][AST]
    float* Vs   = Ssm + 64 * AST;        // [64][VST]
    float* part = Vs  + 64 * VST;        // [4][64]
    float* rsum = part + 256;            // [64]

    const int tid  = threadIdx.x;
    const int warp = tid >> 5, lane = tid & 31;
    const int g    = lane >> 2, t = lane & 3;
    const int wm   = warp >> 2;          // 0..1
    const int wn   = warp & 3;           // 0..3
    const int sb   = blockIdx.x, bh = blockIdx.y;
    const int b    = bh / HEADS, h = bh % HEADS;
    const int s0   = sb * 64;

    if (tid < 64) rsum[tid] = 0.f;

    // Q tile (64x64), tf32-rounded
#pragma unroll
    for (int l = 0; l < 4; l++) {
        int lin = tid + l * 256, r = lin >> 4, c4 = (lin & 15) << 2;
        float4 x = *(const float4*)&q[(size_t)(b * Ss + s0 + r) * Hh + h * KD + c4];
        float4 y = { to_tf32(x.x), to_tf32(x.y), to_tf32(x.z), to_tf32(x.w) };
        *(float4*)&Qs[r * AST + c4] = y;
    }

    float oacc[2][4][4];
#pragma unroll
    for (int mi = 0; mi < 2; mi++)
#pragma unroll
        for (int nj = 0; nj < 4; nj++)
#pragma unroll
            for (int r = 0; r < 4; r++) oacc[mi][nj][r] = 0.f;

    __syncthreads();

    const size_t mbase = (size_t)h * Ss * Ss;

    for (int tt = 0; tt <= sb; tt++) {
        const int t0 = tt * 64;

        // K tile (64x64) and V tile (64x128), tf32-rounded
#pragma unroll
        for (int l = 0; l < 4; l++) {
            int lin = tid + l * 256, r = lin >> 4, c4 = (lin & 15) << 2;
            float4 x = *(const float4*)&k[(size_t)(b * Ss + t0 + r) * Hh + h * KD + c4];
            float4 y = { to_tf32(x.x), to_tf32(x.y), to_tf32(x.z), to_tf32(x.w) };
            *(float4*)&Ks[r * AST + c4] = y;
        }
#pragma unroll
        for (int l = 0; l < 8; l++) {
            int lin = tid + l * 256, r = lin >> 5, c4 = (lin & 31) << 2;
            float4 x = *(const float4*)&v[(size_t)(b * Ss + t0 + r) * VD + h * HD + c4];
            float4 y = { to_tf32(x.x), to_tf32(x.y), to_tf32(x.z), to_tf32(x.w) };
            *(float4*)&Vs[r * VST + c4] = y;
        }
        __syncthreads();

        // ---- S = Q * K^T : warp tile 32x16 of the 64x64 S ------------------
        float sacc[2][2][4];
#pragma unroll
        for (int mi = 0; mi < 2; mi++)
#pragma unroll
            for (int nj = 0; nj < 2; nj++)
#pragma unroll
                for (int r = 0; r < 4; r++) sacc[mi][nj][r] = 0.f;

#pragma unroll
        for (int ks = 0; ks < 8; ks++) {
            const int kb = ks * 8;
            unsigned af[2][4];
#pragma unroll
            for (int mi = 0; mi < 2; mi++) {
                int mb = wm * 32 + mi * 16 + g;
                af[mi][0] = __float_as_uint(Qs[(mb    ) * AST + kb + t    ]);
                af[mi][1] = __float_as_uint(Qs[(mb + 8) * AST + kb + t    ]);
                af[mi][2] = __float_as_uint(Qs[(mb    ) * AST + kb + t + 4]);
                af[mi][3] = __float_as_uint(Qs[(mb + 8) * AST + kb + t + 4]);
            }
            unsigned bf[2][2];
#pragma unroll
            for (int nj = 0; nj < 2; nj++) {
                int nb = wn * 16 + nj * 8 + g;
                bf[nj][0] = __float_as_uint(Ks[nb * AST + kb + t    ]);
                bf[nj][1] = __float_as_uint(Ks[nb * AST + kb + t + 4]);
            }
#pragma unroll
            for (int mi = 0; mi < 2; mi++)
#pragma unroll
                for (int nj = 0; nj < 2; nj++)
                    MMA_TF32(sacc[mi][nj], af[mi], bf[nj]);
        }

        // ---- mask in regs, partial rowsums, stash tf32 S -------------------
        float pr[2][2] = { {0.f, 0.f}, {0.f, 0.f} };   // [mi][row g / g+8]
#pragma unroll
        for (int mi = 0; mi < 2; mi++) {
            int r0 = wm * 32 + mi * 16 + g;
#pragma unroll
            for (int nj = 0; nj < 2; nj++) {
                int col = wn * 16 + nj * 8 + 2 * t;
                float2 m0 = *(const float2*)&mask[mbase + (size_t)(s0 + r0    ) * Ss + t0 + col];
                float2 m1 = *(const float2*)&mask[mbase + (size_t)(s0 + r0 + 8) * Ss + t0 + col];
                float v0 = sacc[mi][nj][0] * m0.x;
                float v1 = sacc[mi][nj][1] * m0.y;
                float v2 = sacc[mi][nj][2] * m1.x;
                float v3 = sacc[mi][nj][3] * m1.y;
                pr[mi][0] += v0 + v1;
                pr[mi][1] += v2 + v3;
                float2 s01 = { to_tf32(v0), to_tf32(v1) };
                float2 s23 = { to_tf32(v2), to_tf32(v3) };
                *(float2*)&Ssm[(r0    ) * AST + col] = s01;
                *(float2*)&Ssm[(r0 + 8) * AST + col] = s23;
            }
        }
#pragma unroll
        for (int mi = 0; mi < 2; mi++)
#pragma unroll
            for (int rr = 0; rr < 2; rr++) {
                float p = pr[mi][rr];
                p += __shfl_xor_sync(0xffffffffu, p, 1);
                p += __shfl_xor_sync(0xffffffffu, p, 2);
                if (t == 0) part[wn * 64 + wm * 32 + mi * 16 + rr * 8 + g] = p;
            }
        __syncthreads();

        // deterministic fixed-order rowsum accumulation
        if (tid < 64)
            rsum[tid] += (part[tid] + part[64 + tid]) + (part[128 + tid] + part[192 + tid]);

        // ---- O += S * V : warp tile 32x32 of the 64x128 O ------------------
#pragma unroll
        for (int ks = 0; ks < 8; ks++) {
            const int kb = ks * 8;
            unsigned af[2][4];
#pragma unroll
            for (int mi = 0; mi < 2; mi++) {
                int mb = wm * 32 + mi * 16 + g;
                af[mi][0] = __float_as_uint(Ssm[(mb    ) * AST + kb + t    ]);
                af[mi][1] = __float_as_uint(Ssm[(mb + 8) * AST + kb + t    ]);
                af[mi][2] = __float_as_uint(Ssm[(mb    ) * AST + kb + t + 4]);
                af[mi][3] = __float_as_uint(Ssm[(mb + 8) * AST + kb + t + 4]);
            }
            unsigned bf[4][2];
#pragma unroll
            for (int nj = 0; nj < 4; nj++) {
                int nb = wn * 32 + nj * 8 + g;
                bf[nj][0] = __float_as_uint(Vs[(kb + t    ) * VST + nb]);
                bf[nj][1] = __float_as_uint(Vs[(kb + t + 4) * VST + nb]);
            }
#pragma unroll
            for (int mi = 0; mi < 2; mi++)
#pragma unroll
                for (int nj = 0; nj < 4; nj++)
                    MMA_TF32(oacc[mi][nj], af[mi], bf[nj]);
        }
        __syncthreads();
    }

    // ---- normalize and write ----------------------------------------------
#pragma unroll
    for (int mi = 0; mi < 2; mi++) {
        int r0 = wm * 32 + mi * 16 + g;
        float i0 = 1.f / fmaxf(fabsf(rsum[r0    ]), 1.f);
        float i1 = 1.f / fmaxf(fabsf(rsum[r0 + 8]), 1.f);
#pragma unroll
        for (int nj = 0; nj < 4; nj++) {
            int col = h * HD + wn * 32 + nj * 8 + 2 * t;
            float2 o01 = { oacc[mi][nj][0] * i0, oacc[mi][nj][1] * i0 };
            float2 o23 = { oacc[mi][nj][2] * i1, oacc[mi][nj][3] * i1 };
            *(float2*)&ao[(size_t)(b * Ss + s0 + r0    ) * VD + col] = o01;
            *(float2*)&ao[(size_t)(b * Ss + s0 + r0 + 8) * VD + col] = o23;
        }
    }
}

// ---------------- group RMS-norm (per head, 128 dims) + SiLU gate ----------
__global__ void gnorm_gate(float* __restrict__ ao, const float* __restrict__ g)
{
    int gid  = (blockIdx.x * blockDim.x + threadIdx.x) >> 5;
    int lane = threadIdx.x & 31;
    if (gid >= MS * HEADS) return;
    int row = gid / HEADS;
    int hh  = gid % HEADS;
    size_t base = (size_t)row * VD + hh * HD + lane * 4;

    float4 x = *(const float4*)&ao[base];
    float ss = x.x*x.x + x.y*x.y + x.z*x.z + x.w*x.w;
#pragma unroll
    for (int o = 16; o > 0; o >>= 1) ss += __shfl_xor_sync(0xffffffffu, ss, o);
    float r = rsqrtf(ss * (1.f / 128.f) + 1e-5f);

    float4 gv = *(const float4*)&g[base];
    float4 o;
    o.x = x.x * r * gv.x * (1.f / (1.f + __expf(-gv.x)));
    o.y = x.y * r * gv.y * (1.f / (1.f + __expf(-gv.y)));
    o.z = x.z * r * gv.z * (1.f / (1.f + __expf(-gv.z)));
    o.w = x.w * r * gv.w * (1.f / (1.f + __expf(-gv.w)));
    *(float4*)&ao[base] = o;
}

// ---------------- launcher -------------------------------------------------
extern "C" void kernel_launch(void* const* d_in, const int* in_sizes, int n_in,
                              void* d_out, int out_size)
{
    const float* x    = (const float*)d_in[0];
    const float* sn   = (const float*)d_in[1];
    const float* cs   = (const float*)d_in[2];
    const float* mask = (const float*)d_in[3];
    const float* Wq   = (const float*)d_in[4];
    const float* Wk   = (const float*)d_in[5];
    const float* Wv   = (const float*)d_in[6];
    const float* Wg   = (const float*)d_in[7];
    const float* Wo   = (const float*)d_in[8];
    float* out = (float*)d_out;

    float *q, *k, *v, *g, *ao;
    cudaGetSymbolAddress((void**)&q,  g_q);
    cudaGetSymbolAddress((void**)&k,  g_k);
    cudaGetSymbolAddress((void**)&v,  g_v);
    cudaGetSymbolAddress((void**)&g,  g_g);
    cudaGetSymbolAddress((void**)&ao, g_ao);

    const int attn_smem = (3 * 64 * AST + 64 * VST + 256 + 64) * (int)sizeof(float);
    cudaFuncSetAttribute(attn_tc, cudaFuncAttributeMaxDynamicSharedMemorySize,
                         attn_smem);

    dim3 gN1(Hh / 128, MS / 128);   // (8, 32)
    dim3 gN2(VD / 128, MS / 128);   // (16, 32)

    gemm_nt_tc<<<gN1, 256>>>(x, Wq, q, MS, Hh, Hh, 1.0f);
    gemm_nt_tc<<<gN1, 256>>>(x, Wk, k, MS, Hh, Hh, 0.125f);   // kd^-0.5 = 1/8
    gemm_nt_tc<<<gN2, 256>>>(x, Wv, v, MS, VD, Hh, 1.0f);
    gemm_nt_tc<<<gN2, 256>>>(x, Wg, g, MS, VD, Hh, 1.0f);

    rope_kernel<<<(MS * Hh / 2 + 255) / 256, 256>>>(q, k, sn, cs);

    attn_tc<<<dim3(Ss / 64, Bb * HEADS), 256, attn_smem>>>(q, k, v, mask, ao);

    gnorm_gate<<<(MS * HEADS * 32 + 255) / 256, 256>>>(ao, g);

    gemm_nt_tc<<<dim3(Hh / 128, MS / 128), 256>>>(ao, Wo, out, MS, Hh, VD, 1.0f);
}

// round 7
// speedup vs baseline: 2.6344x; 1.1365x over previous
#include <cuda_runtime.h>

#define Bb 2
#define Ss 2048
#define Hh 1024
#define HEADS 16
#define KD 64
#define VD 2048
#define HD 128
#define MS (Bb*Ss)   /* 4096 rows */

// ---------------- scratch (device globals; no allocation allowed) ----------
__device__ float g_q [MS*Hh];
__device__ float g_k [MS*Hh];
__device__ float g_v [MS*VD];
__device__ float g_g [MS*VD];
__device__ float g_ao[MS*VD];

// ---------------- helpers --------------------------------------------------
__device__ __forceinline__ float to_tf32(float x) {
    unsigned u;
    asm("cvt.rna.tf32.f32 %0, %1;" : "=r"(u) : "f"(x));
    return __uint_as_float(u);
}

#define MMA_TF32(c, a, b)                                                     \
    asm volatile(                                                             \
        "mma.sync.aligned.m16n8k8.row.col.f32.tf32.tf32.f32 "                 \
        "{%0,%1,%2,%3}, {%4,%5,%6,%7}, {%8,%9}, {%0,%1,%2,%3};"               \
        : "+f"((c)[0]), "+f"((c)[1]), "+f"((c)[2]), "+f"((c)[3])              \
        : "r"((a)[0]), "r"((a)[1]), "r"((a)[2]), "r"((a)[3]),                 \
          "r"((b)[0]), "r"((b)[1]))

// ============================================================================
// Core 128x128 tf32 GEMM body: C = alpha * A(MxK) * B(NxK)^T, optional rope.
// Smem layout: addr = k*128 + (m ^ swz(k)), swz(k) = 4*(k&7) ^ (k&8).
// Conflict-free for BOTH cooperative stores and MMA fragment loads.
// Double-buffered (2 stages x 8KB per operand), one barrier per k16 iter.
// ============================================================================
__device__ __forceinline__ void gemm128_body(
    const float* __restrict__ A, const float* __restrict__ Bm,
    float* __restrict__ C, int N, int K, float alpha,
    int m0, int n0, bool rope,
    const float* __restrict__ sn, const float* __restrict__ cs,
    float* As, float* Bs)
{
    const int tid  = threadIdx.x;
    const int warp = tid >> 5, lane = tid & 31;
    const int g    = lane >> 2, t = lane & 3;
    const int wm   = warp >> 2;      // 0..1
    const int wn   = warp & 3;       // 0..3
    const int row  = tid >> 2;       // 0..63
    const int c4   = (tid & 3) * 4;  // 0,4,8,12

    float acc[4][4][4];
#pragma unroll
    for (int i = 0; i < 4; i++)
#pragma unroll
        for (int j = 0; j < 4; j++)
#pragma unroll
            for (int r = 0; r < 4; r++) acc[i][j][r] = 0.f;

    const float* Ap = A  + (size_t)(m0 + row) * K + c4;
    const float* Bp = Bm + (size_t)(n0 + row) * K + c4;
    const size_t arow64 = (size_t)64 * K;

    float4 ra0 = *(const float4*)Ap;
    float4 ra1 = *(const float4*)(Ap + arow64);
    float4 rb0 = *(const float4*)Bp;
    float4 rb1 = *(const float4*)(Bp + arow64);

    // precompute store offsets (stage-relative): o[j] for k=c4+j, m=row
    int soff[4];
#pragma unroll
    for (int j = 0; j < 4; j++) {
        int k  = c4 + j;
        int sw = ((k & 7) << 2) ^ (k & 8);
        soff[j] = k * 128 + (row ^ sw);
    }

    int stage = 0;
    {   // store tile 0
        float* Ad = As; float* Bd = Bs;
        float a0[4] = {ra0.x, ra0.y, ra0.z, ra0.w};
        float a1[4] = {ra1.x, ra1.y, ra1.z, ra1.w};
        float b0[4] = {rb0.x, rb0.y, rb0.z, rb0.w};
        float b1[4] = {rb1.x, rb1.y, rb1.z, rb1.w};
#pragma unroll
        for (int j = 0; j < 4; j++) {
            Ad[soff[j]]      = to_tf32(a0[j]);
            Ad[soff[j] + 64] = to_tf32(a1[j]);
            Bd[soff[j]]      = to_tf32(b0[j]);
            Bd[soff[j] + 64] = to_tf32(b1[j]);
        }
    }
    __syncthreads();

    for (int k0 = 16; k0 <= K; k0 += 16) {
        const bool more = (k0 < K);
        if (more) {
            ra0 = *(const float4*)(Ap + k0);
            ra1 = *(const float4*)(Ap + arow64 + k0);
            rb0 = *(const float4*)(Bp + k0);
            rb1 = *(const float4*)(Bp + arow64 + k0);
        }

        const float* Ar = As + stage * 2048;
        const float* Br = Bs + stage * 2048;
#pragma unroll
        for (int ks = 0; ks < 2; ks++) {
            const int kb  = ks * 8;
            const int sw1 = (4 * t) ^ kb;           // k = kb+t
            const int sw2 = (4 * t + 16) ^ kb;      // k = kb+t+4
            const float* r1 = Ar + (kb + t) * 128;
            const float* r2 = Ar + (kb + t + 4) * 128;
            unsigned af[4][4];
#pragma unroll
            for (int mi = 0; mi < 4; mi++) {
                int mb = wm * 64 + mi * 16 + g;
                af[mi][0] = __float_as_uint(r1[ mb      ^ sw1]);
                af[mi][1] = __float_as_uint(r1[(mb + 8) ^ sw1]);
                af[mi][2] = __float_as_uint(r2[ mb      ^ sw2]);
                af[mi][3] = __float_as_uint(r2[(mb + 8) ^ sw2]);
            }
            const float* q1 = Br + (kb + t) * 128;
            const float* q2 = Br + (kb + t + 4) * 128;
            unsigned bf[4][2];
#pragma unroll
            for (int nj = 0; nj < 4; nj++) {
                int nb = wn * 32 + nj * 8 + g;
                bf[nj][0] = __float_as_uint(q1[nb ^ sw1]);
                bf[nj][1] = __float_as_uint(q2[nb ^ sw2]);
            }
#pragma unroll
            for (int mi = 0; mi < 4; mi++)
#pragma unroll
                for (int nj = 0; nj < 4; nj++)
                    MMA_TF32(acc[mi][nj], af[mi], bf[nj]);
        }

        if (more) {
            float* Ad = As + (stage ^ 1) * 2048;
            float* Bd = Bs + (stage ^ 1) * 2048;
            float a0[4] = {ra0.x, ra0.y, ra0.z, ra0.w};
            float a1[4] = {ra1.x, ra1.y, ra1.z, ra1.w};
            float b0[4] = {rb0.x, rb0.y, rb0.z, rb0.w};
            float b1[4] = {rb1.x, rb1.y, rb1.z, rb1.w};
#pragma unroll
            for (int j = 0; j < 4; j++) {
                Ad[soff[j]]      = to_tf32(a0[j]);
                Ad[soff[j] + 64] = to_tf32(a1[j]);
                Bd[soff[j]]      = to_tf32(b0[j]);
                Bd[soff[j] + 64] = to_tf32(b1[j]);
            }
        }
        __syncthreads();
        stage ^= 1;
    }

    // ---- epilogue (optional fused rotary for q/k segments) -----------------
#pragma unroll
    for (int mi = 0; mi < 4; mi++) {
        int r0  = m0 + wm * 64 + mi * 16 + g;
        int sA  = r0 & (Ss - 1);
        int sB  = (r0 + 8) & (Ss - 1);
#pragma unroll
        for (int nj = 0; nj < 4; nj++) {
            int col = n0 + wn * 32 + nj * 8 + 2 * t;
            float e0 = alpha * acc[mi][nj][0];
            float o0 = alpha * acc[mi][nj][1];
            float e1 = alpha * acc[mi][nj][2];
            float o1 = alpha * acc[mi][nj][3];
            if (rope) {
                int hc = col & 63;
                float2 cA = *(const float2*)&cs[sA * KD + hc];
                float2 sAv= *(const float2*)&sn[sA * KD + hc];
                float2 cB = *(const float2*)&cs[sB * KD + hc];
                float2 sBv= *(const float2*)&sn[sB * KD + hc];
                float ne0 = e0 * cA.x - o0 * sAv.x;
                float no0 = o0 * cA.y + e0 * sAv.y;
                float ne1 = e1 * cB.x - o1 * sBv.x;
                float no1 = o1 * cB.y + e1 * sBv.y;
                e0 = ne0; o0 = no0; e1 = ne1; o1 = no1;
            }
            float2 w01 = { e0, o0 };
            float2 w23 = { e1, o1 };
            *(float2*)&C[(size_t)r0 * N + col]       = w01;
            *(float2*)&C[(size_t)(r0 + 8) * N + col] = w23;
        }
    }
}

// ---------------- fused Q/K/V/G projections (+rope on q,k) -----------------
__global__ __launch_bounds__(256, 2)
void proj_qkvg(const float* __restrict__ x,
               const float* __restrict__ Wq, const float* __restrict__ Wk,
               const float* __restrict__ Wv, const float* __restrict__ Wg,
               const float* __restrict__ sn, const float* __restrict__ cs,
               float* __restrict__ q, float* __restrict__ k,
               float* __restrict__ v, float* __restrict__ g)
{
    __shared__ float As[2 * 2048];
    __shared__ float Bs[2 * 2048];
    const int bx = blockIdx.x;
    const float* Bm; float* Cp; int Nloc; float alpha; bool rope; int nb;
    if (bx < 8)       { Bm = Wq; Cp = q; Nloc = 1024; alpha = 1.f;    rope = true;  nb = bx; }
    else if (bx < 16) { Bm = Wk; Cp = k; Nloc = 1024; alpha = 0.125f; rope = true;  nb = bx - 8; }
    else if (bx < 32) { Bm = Wv; Cp = v; Nloc = 2048; alpha = 1.f;    rope = false; nb = bx - 16; }
    else              { Bm = Wg; Cp = g; Nloc = 2048; alpha = 1.f;    rope = false; nb = bx - 32; }
    gemm128_body(x, Bm, Cp, Nloc, Hh, alpha, blockIdx.y * 128, nb * 128,
                 rope, sn, cs, As, Bs);
}

// ---------------- output projection ----------------------------------------
__global__ __launch_bounds__(256, 2)
void gemm_out(const float* __restrict__ A, const float* __restrict__ Bm,
              float* __restrict__ C)
{
    __shared__ float As[2 * 2048];
    __shared__ float Bs[2 * 2048];
    gemm128_body(A, Bm, C, Hh, VD, 1.f, blockIdx.y * 128, blockIdx.x * 128,
                 false, nullptr, nullptr, As, Bs);
}

// ---------------- retention attention (tf32 tensor-core) --------------------
#define AST 68
#define VST 136
__global__ __launch_bounds__(256, 2)
void attn_tc(const float* __restrict__ q, const float* __restrict__ k,
             const float* __restrict__ v, const float* __restrict__ mask,
             float* __restrict__ ao)
{
    extern __shared__ float sm[];
    float* Qs   = sm;                    // [64][AST]
    float* Ks   = Qs  + 64 * AST;        // [64][AST]
    float* Ssm  = Ks  + 64 * AST;        // [64][AST]
    float* Vs   = Ssm + 64 * AST;        // [64][VST]
    float* part = Vs  + 64 * VST;        // [4][64]
    float* rsum = part + 256;            // [64]

    const int tid  = threadIdx.x;
    const int warp = tid >> 5, lane = tid & 31;
    const int g    = lane >> 2, t = lane & 3;
    const int wm   = warp >> 2;          // 0..1
    const int wn   = warp & 3;           // 0..3
    const int sb   = blockIdx.x, bh = blockIdx.y;
    const int b    = bh / HEADS, h = bh % HEADS;
    const int s0   = sb * 64;

    if (tid < 64) rsum[tid] = 0.f;

#pragma unroll
    for (int l = 0; l < 4; l++) {
        int lin = tid + l * 256, r = lin >> 4, c4 = (lin & 15) << 2;
        float4 x = *(const float4*)&q[(size_t)(b * Ss + s0 + r) * Hh + h * KD + c4];
        float4 y = { to_tf32(x.x), to_tf32(x.y), to_tf32(x.z), to_tf32(x.w) };
        *(float4*)&Qs[r * AST + c4] = y;
    }

    float oacc[2][4][4];
#pragma unroll
    for (int mi = 0; mi < 2; mi++)
#pragma unroll
        for (int nj = 0; nj < 4; nj++)
#pragma unroll
            for (int r = 0; r < 4; r++) oacc[mi][nj][r] = 0.f;

    __syncthreads();

    const size_t mbase = (size_t)h * Ss * Ss;

    for (int tt = 0; tt <= sb; tt++) {
        const int t0 = tt * 64;

#pragma unroll
        for (int l = 0; l < 4; l++) {
            int lin = tid + l * 256, r = lin >> 4, c4 = (lin & 15) << 2;
            float4 x = *(const float4*)&k[(size_t)(b * Ss + t0 + r) * Hh + h * KD + c4];
            float4 y = { to_tf32(x.x), to_tf32(x.y), to_tf32(x.z), to_tf32(x.w) };
            *(float4*)&Ks[r * AST + c4] = y;
        }
#pragma unroll
        for (int l = 0; l < 8; l++) {
            int lin = tid + l * 256, r = lin >> 5, c4 = (lin & 31) << 2;
            float4 x = *(const float4*)&v[(size_t)(b * Ss + t0 + r) * VD + h * HD + c4];
            float4 y = { to_tf32(x.x), to_tf32(x.y), to_tf32(x.z), to_tf32(x.w) };
            *(float4*)&Vs[r * VST + c4] = y;
        }
        __syncthreads();

        float sacc[2][2][4];
#pragma unroll
        for (int mi = 0; mi < 2; mi++)
#pragma unroll
            for (int nj = 0; nj < 2; nj++)
#pragma unroll
                for (int r = 0; r < 4; r++) sacc[mi][nj][r] = 0.f;

#pragma unroll
        for (int ks = 0; ks < 8; ks++) {
            const int kb = ks * 8;
            unsigned af[2][4];
#pragma unroll
            for (int mi = 0; mi < 2; mi++) {
                int mb = wm * 32 + mi * 16 + g;
                af[mi][0] = __float_as_uint(Qs[(mb    ) * AST + kb + t    ]);
                af[mi][1] = __float_as_uint(Qs[(mb + 8) * AST + kb + t    ]);
                af[mi][2] = __float_as_uint(Qs[(mb    ) * AST + kb + t + 4]);
                af[mi][3] = __float_as_uint(Qs[(mb + 8) * AST + kb + t + 4]);
            }
            unsigned bf[2][2];
#pragma unroll
            for (int nj = 0; nj < 2; nj++) {
                int nb = wn * 16 + nj * 8 + g;
                bf[nj][0] = __float_as_uint(Ks[nb * AST + kb + t    ]);
                bf[nj][1] = __float_as_uint(Ks[nb * AST + kb + t + 4]);
            }
#pragma unroll
            for (int mi = 0; mi < 2; mi++)
#pragma unroll
                for (int nj = 0; nj < 2; nj++)
                    MMA_TF32(sacc[mi][nj], af[mi], bf[nj]);
        }

        float pr[2][2] = { {0.f, 0.f}, {0.f, 0.f} };
#pragma unroll
        for (int mi = 0; mi < 2; mi++) {
            int r0 = wm * 32 + mi * 16 + g;
#pragma unroll
            for (int nj = 0; nj < 2; nj++) {
                int col = wn * 16 + nj * 8 + 2 * t;
                float2 m0 = *(const float2*)&mask[mbase + (size_t)(s0 + r0    ) * Ss + t0 + col];
                float2 m1 = *(const float2*)&mask[mbase + (size_t)(s0 + r0 + 8) * Ss + t0 + col];
                float v0 = sacc[mi][nj][0] * m0.x;
                float v1 = sacc[mi][nj][1] * m0.y;
                float v2 = sacc[mi][nj][2] * m1.x;
                float v3 = sacc[mi][nj][3] * m1.y;
                pr[mi][0] += v0 + v1;
                pr[mi][1] += v2 + v3;
                float2 s01 = { to_tf32(v0), to_tf32(v1) };
                float2 s23 = { to_tf32(v2), to_tf32(v3) };
                *(float2*)&Ssm[(r0    ) * AST + col] = s01;
                *(float2*)&Ssm[(r0 + 8) * AST + col] = s23;
            }
        }
#pragma unroll
        for (int mi = 0; mi < 2; mi++)
#pragma unroll
            for (int rr = 0; rr < 2; rr++) {
                float p = pr[mi][rr];
                p += __shfl_xor_sync(0xffffffffu, p, 1);
                p += __shfl_xor_sync(0xffffffffu, p, 2);
                if (t == 0) part[wn * 64 + wm * 32 + mi * 16 + rr * 8 + g] = p;
            }
        __syncthreads();

        if (tid < 64)
            rsum[tid] += (part[tid] + part[64 + tid]) + (part[128 + tid] + part[192 + tid]);

#pragma unroll
        for (int ks = 0; ks < 8; ks++) {
            const int kb = ks * 8;
            unsigned af[2][4];
#pragma unroll
            for (int mi = 0; mi < 2; mi++) {
                int mb = wm * 32 + mi * 16 + g;
                af[mi][0] = __float_as_uint(Ssm[(mb    ) * AST + kb + t    ]);
                af[mi][1] = __float_as_uint(Ssm[(mb + 8) * AST + kb + t    ]);
                af[mi][2] = __float_as_uint(Ssm[(mb    ) * AST + kb + t + 4]);
                af[mi][3] = __float_as_uint(Ssm[(mb + 8) * AST + kb + t + 4]);
            }
            unsigned bf[4][2];
#pragma unroll
            for (int nj = 0; nj < 4; nj++) {
                int nb = wn * 32 + nj * 8 + g;
                bf[nj][0] = __float_as_uint(Vs[(kb + t    ) * VST + nb]);
                bf[nj][1] = __float_as_uint(Vs[(kb + t + 4) * VST + nb]);
            }
#pragma unroll
            for (int mi = 0; mi < 2; mi++)
#pragma unroll
                for (int nj = 0; nj < 4; nj++)
                    MMA_TF32(oacc[mi][nj], af[mi], bf[nj]);
        }
        __syncthreads();
    }

#pragma unroll
    for (int mi = 0; mi < 2; mi++) {
        int r0 = wm * 32 + mi * 16 + g;
        float i0 = 1.f / fmaxf(fabsf(rsum[r0    ]), 1.f);
        float i1 = 1.f / fmaxf(fabsf(rsum[r0 + 8]), 1.f);
#pragma unroll
        for (int nj = 0; nj < 4; nj++) {
            int col = h * HD + wn * 32 + nj * 8 + 2 * t;
            float2 o01 = { oacc[mi][nj][0] * i0, oacc[mi][nj][1] * i0 };
            float2 o23 = { oacc[mi][nj][2] * i1, oacc[mi][nj][3] * i1 };
            *(float2*)&ao[(size_t)(b * Ss + s0 + r0    ) * VD + col] = o01;
            *(float2*)&ao[(size_t)(b * Ss + s0 + r0 + 8) * VD + col] = o23;
        }
    }
}

// ---------------- group RMS-norm (per head, 128 dims) + SiLU gate ----------
__global__ void gnorm_gate(float* __restrict__ ao, const float* __restrict__ g)
{
    int gid  = (blockIdx.x * blockDim.x + threadIdx.x) >> 5;
    int lane = threadIdx.x & 31;
    if (gid >= MS * HEADS) return;
    int row = gid / HEADS;
    int hh  = gid % HEADS;
    size_t base = (size_t)row * VD + hh * HD + lane * 4;

    float4 x = *(const float4*)&ao[base];
    float ss = x.x*x.x + x.y*x.y + x.z*x.z + x.w*x.w;
#pragma unroll
    for (int o = 16; o > 0; o >>= 1) ss += __shfl_xor_sync(0xffffffffu, ss, o);
    float r = rsqrtf(ss * (1.f / 128.f) + 1e-5f);

    float4 gv = *(const float4*)&g[base];
    float4 o;
    o.x = x.x * r * gv.x * (1.f / (1.f + __expf(-gv.x)));
    o.y = x.y * r * gv.y * (1.f / (1.f + __expf(-gv.y)));
    o.z = x.z * r * gv.z * (1.f / (1.f + __expf(-gv.z)));
    o.w = x.w * r * gv.w * (1.f / (1.f + __expf(-gv.w)));
    *(float4*)&ao[base] = o;
}

// ---------------- launcher -------------------------------------------------
extern "C" void kernel_launch(void* const* d_in, const int* in_sizes, int n_in,
                              void* d_out, int out_size)
{
    const float* x    = (const float*)d_in[0];
    const float* sn   = (const float*)d_in[1];
    const float* cs   = (const float*)d_in[2];
    const float* mask = (const float*)d_in[3];
    const float* Wq   = (const float*)d_in[4];
    const float* Wk   = (const float*)d_in[5];
    const float* Wv   = (const float*)d_in[6];
    const float* Wg   = (const float*)d_in[7];
    const float* Wo   = (const float*)d_in[8];
    float* out = (float*)d_out;

    float *q, *k, *v, *g, *ao;
    cudaGetSymbolAddress((void**)&q,  g_q);
    cudaGetSymbolAddress((void**)&k,  g_k);
    cudaGetSymbolAddress((void**)&v,  g_v);
    cudaGetSymbolAddress((void**)&g,  g_g);
    cudaGetSymbolAddress((void**)&ao, g_ao);

    const int attn_smem = (3 * 64 * AST + 64 * VST + 256 + 64) * (int)sizeof(float);
    cudaFuncSetAttribute(attn_tc, cudaFuncAttributeMaxDynamicSharedMemorySize,
                         attn_smem);

    proj_qkvg<<<dim3(48, 32), 256>>>(x, Wq, Wk, Wv, Wg, sn, cs, q, k, v, g);

    attn_tc<<<dim3(Ss / 64, Bb * HEADS), 256, attn_smem>>>(q, k, v, mask, ao);

    gnorm_gate<<<(MS * HEADS * 32 + 255) / 256, 256>>>(ao, g);

    gemm_out<<<dim3(8, 32), 256>>>(ao, Wo, out);
}

// round 8
// speedup vs baseline: 3.3645x; 1.2771x over previous
#include <cuda_runtime.h>

#define Bb 2
#define Ss 2048
#define Hh 1024
#define HEADS 16
#define KD 64
#define VD 2048
#define HD 128
#define MS (Bb*Ss)   /* 4096 rows */

// ---------------- scratch (device globals; no allocation allowed) ----------
__device__ float g_q [MS*Hh];
__device__ float g_k [MS*Hh];
__device__ float g_v [MS*VD];
__device__ float g_g [MS*VD];
__device__ float g_ao[MS*VD];

// ---------------- helpers --------------------------------------------------
__device__ __forceinline__ float to_tf32(float x) {
    unsigned u;
    asm("cvt.rna.tf32.f32 %0, %1;" : "=r"(u) : "f"(x));
    return __uint_as_float(u);
}

#define MMA_TF32(c, a, b)                                                     \
    asm volatile(                                                             \
        "mma.sync.aligned.m16n8k8.row.col.f32.tf32.tf32.f32 "                 \
        "{%0,%1,%2,%3}, {%4,%5,%6,%7}, {%8,%9}, {%0,%1,%2,%3};"               \
        : "+f"((c)[0]), "+f"((c)[1]), "+f"((c)[2]), "+f"((c)[3])              \
        : "r"((a)[0]), "r"((a)[1]), "r"((a)[2]), "r"((a)[3]),                 \
          "r"((b)[0]), "r"((b)[1]))

__device__ __forceinline__ void ldsm4(unsigned r[4], unsigned addr) {
    asm volatile("ldmatrix.sync.aligned.m8n8.x4.shared.b16 {%0,%1,%2,%3}, [%4];"
                 : "=r"(r[0]), "=r"(r[1]), "=r"(r[2]), "=r"(r[3]) : "r"(addr));
}

// ============================================================================
// Core 128x128 tf32 GEMM body: C = alpha * A(MxK) * B(NxK)^T, optional rope.
// Smem tile: [128 m][16 k] floats as float4 chunks, chunk' = k4 ^ ((m>>1)&3).
// Conflict-free for STS.128 cooperative stores AND ldmatrix.x4 fragment loads.
// Double-buffered (2 stages x 8KB per operand), one barrier per k16 iter.
// ============================================================================
__device__ __forceinline__ void gemm128_body(
    const float* __restrict__ A, const float* __restrict__ Bm,
    float* __restrict__ C, int N, int K, float alpha,
    int m0, int n0, bool rope,
    const float* __restrict__ sn, const float* __restrict__ cs,
    float* As, float* Bs)
{
    const int tid  = threadIdx.x;
    const int warp = tid >> 5, lane = tid & 31;
    const int g    = lane >> 2, t = lane & 3;
    const int wm   = warp >> 2;      // 0..1
    const int wn   = warp & 3;       // 0..3
    const int row  = tid >> 2;       // 0..63
    const int k4   = tid & 3;        // chunk 0..3

    float acc[4][4][4];
#pragma unroll
    for (int i = 0; i < 4; i++)
#pragma unroll
        for (int j = 0; j < 4; j++)
#pragma unroll
            for (int r = 0; r < 4; r++) acc[i][j][r] = 0.f;

    const float* Ap = A  + (size_t)(m0 + row) * K + k4 * 4;
    const float* Bp = Bm + (size_t)(n0 + row) * K + k4 * 4;
    const size_t arow64 = (size_t)64 * K;

    float4 ra0 = *(const float4*)Ap;
    float4 ra1 = *(const float4*)(Ap + arow64);
    float4 rb0 = *(const float4*)Bp;
    float4 rb1 = *(const float4*)(Bp + arow64);

    // store index in float4 units (stage-relative); row+64 has same swizzle
    const int sidx = row * 4 + (k4 ^ ((row >> 1) & 3));
    float4* As4 = (float4*)As;
    float4* Bs4 = (float4*)Bs;

    // ldmatrix per-lane address precompute (byte offsets into stage 0)
    const unsigned aBase = (unsigned)__cvta_generic_to_shared(As);
    const unsigned bBase = (unsigned)__cvta_generic_to_shared(Bs);
    const int sel = lane >> 3;
    // A: matrix sel -> row8 = sel&1, dk = sel>>1
    unsigned a_off[4]; int a_sw[4];
#pragma unroll
    for (int mi = 0; mi < 4; mi++) {
        int mr = wm * 64 + mi * 16 + (sel & 1) * 8 + (lane & 7);
        a_sw[mi]  = (mr >> 1) & 3;
        a_off[mi] = aBase + mr * 64;
    }
    const int dkA = sel >> 1;
    // B: matrix sel -> row8 = sel>>1, dk = sel&1
    unsigned b_off[2]; int b_sw[2];
#pragma unroll
    for (int p = 0; p < 2; p++) {
        int nr = wn * 32 + p * 16 + (sel >> 1) * 8 + (lane & 7);
        b_sw[p]  = (nr >> 1) & 3;
        b_off[p] = bBase + nr * 64;
    }
    const int dkB = sel & 1;

    {   // store tile 0
        As4[sidx]       = make_float4(to_tf32(ra0.x), to_tf32(ra0.y), to_tf32(ra0.z), to_tf32(ra0.w));
        As4[sidx + 256] = make_float4(to_tf32(ra1.x), to_tf32(ra1.y), to_tf32(ra1.z), to_tf32(ra1.w));
        Bs4[sidx]       = make_float4(to_tf32(rb0.x), to_tf32(rb0.y), to_tf32(rb0.z), to_tf32(rb0.w));
        Bs4[sidx + 256] = make_float4(to_tf32(rb1.x), to_tf32(rb1.y), to_tf32(rb1.z), to_tf32(rb1.w));
    }
    __syncthreads();

    int stage = 0;
    for (int k0 = 16; k0 <= K; k0 += 16) {
        const bool more = (k0 < K);
        if (more) {
            ra0 = *(const float4*)(Ap + k0);
            ra1 = *(const float4*)(Ap + arow64 + k0);
            rb0 = *(const float4*)(Bp + k0);
            rb1 = *(const float4*)(Bp + arow64 + k0);
        }

        const unsigned soff = stage * 8192;
#pragma unroll
        for (int ks = 0; ks < 2; ks++) {
            const int ks2 = ks * 2;
            unsigned af[4][4];
#pragma unroll
            for (int mi = 0; mi < 4; mi++)
                ldsm4(af[mi], a_off[mi] + soff + (((ks2 + dkA) ^ a_sw[mi]) << 4));
            unsigned bf[2][4];
#pragma unroll
            for (int p = 0; p < 2; p++)
                ldsm4(bf[p], b_off[p] + soff + (((ks2 + dkB) ^ b_sw[p]) << 4));
#pragma unroll
            for (int mi = 0; mi < 4; mi++)
#pragma unroll
                for (int nj = 0; nj < 4; nj++)
                    MMA_TF32(acc[mi][nj], af[mi], &bf[nj >> 1][(nj & 1) * 2]);
        }

        if (more) {
            const int d = (stage ^ 1) * 512;
            As4[d + sidx]       = make_float4(to_tf32(ra0.x), to_tf32(ra0.y), to_tf32(ra0.z), to_tf32(ra0.w));
            As4[d + sidx + 256] = make_float4(to_tf32(ra1.x), to_tf32(ra1.y), to_tf32(ra1.z), to_tf32(ra1.w));
            Bs4[d + sidx]       = make_float4(to_tf32(rb0.x), to_tf32(rb0.y), to_tf32(rb0.z), to_tf32(rb0.w));
            Bs4[d + sidx + 256] = make_float4(to_tf32(rb1.x), to_tf32(rb1.y), to_tf32(rb1.z), to_tf32(rb1.w));
        }
        __syncthreads();
        stage ^= 1;
    }

    // ---- epilogue (optional fused rotary for q/k segments) -----------------
#pragma unroll
    for (int mi = 0; mi < 4; mi++) {
        int r0  = m0 + wm * 64 + mi * 16 + g;
        int sA  = r0 & (Ss - 1);
        int sB  = (r0 + 8) & (Ss - 1);
#pragma unroll
        for (int nj = 0; nj < 4; nj++) {
            int col = n0 + wn * 32 + nj * 8 + 2 * t;
            float e0 = alpha * acc[mi][nj][0];
            float o0 = alpha * acc[mi][nj][1];
            float e1 = alpha * acc[mi][nj][2];
            float o1 = alpha * acc[mi][nj][3];
            if (rope) {
                int hc = col & 63;
                float2 cA = *(const float2*)&cs[sA * KD + hc];
                float2 sAv= *(const float2*)&sn[sA * KD + hc];
                float2 cB = *(const float2*)&cs[sB * KD + hc];
                float2 sBv= *(const float2*)&sn[sB * KD + hc];
                float ne0 = e0 * cA.x - o0 * sAv.x;
                float no0 = o0 * cA.y + e0 * sAv.y;
                float ne1 = e1 * cB.x - o1 * sBv.x;
                float no1 = o1 * cB.y + e1 * sBv.y;
                e0 = ne0; o0 = no0; e1 = ne1; o1 = no1;
            }
            float2 w01 = { e0, o0 };
            float2 w23 = { e1, o1 };
            *(float2*)&C[(size_t)r0 * N + col]       = w01;
            *(float2*)&C[(size_t)(r0 + 8) * N + col] = w23;
        }
    }
}

// ---------------- fused Q/K/V/G projections (+rope on q,k) -----------------
__global__ __launch_bounds__(256, 2)
void proj_qkvg(const float* __restrict__ x,
               const float* __restrict__ Wq, const float* __restrict__ Wk,
               const float* __restrict__ Wv, const float* __restrict__ Wg,
               const float* __restrict__ sn, const float* __restrict__ cs,
               float* __restrict__ q, float* __restrict__ k,
               float* __restrict__ v, float* __restrict__ g)
{
    __shared__ float As[2 * 2048];
    __shared__ float Bs[2 * 2048];
    const int bx = blockIdx.x;
    const float* Bm; float* Cp; int Nloc; float alpha; bool rope; int nb;
    if (bx < 8)       { Bm = Wq; Cp = q; Nloc = 1024; alpha = 1.f;    rope = true;  nb = bx; }
    else if (bx < 16) { Bm = Wk; Cp = k; Nloc = 1024; alpha = 0.125f; rope = true;  nb = bx - 8; }
    else if (bx < 32) { Bm = Wv; Cp = v; Nloc = 2048; alpha = 1.f;    rope = false; nb = bx - 16; }
    else              { Bm = Wg; Cp = g; Nloc = 2048; alpha = 1.f;    rope = false; nb = bx - 32; }
    gemm128_body(x, Bm, Cp, Nloc, Hh, alpha, blockIdx.y * 128, nb * 128,
                 rope, sn, cs, As, Bs);
}

// ---------------- output projection ----------------------------------------
__global__ __launch_bounds__(256, 2)
void gemm_out(const float* __restrict__ A, const float* __restrict__ Bm,
              float* __restrict__ C)
{
    __shared__ float As[2 * 2048];
    __shared__ float Bs[2 * 2048];
    gemm128_body(A, Bm, C, Hh, VD, 1.f, blockIdx.y * 128, blockIdx.x * 128,
                 false, nullptr, nullptr, As, Bs);
}

// ---------------- retention attention (tf32 TC) + fused gnorm/gate ---------
#define AST 68
#define VST 136
__global__ __launch_bounds__(256, 2)
void attn_tc(const float* __restrict__ q, const float* __restrict__ k,
             const float* __restrict__ v, const float* __restrict__ mask,
             const float* __restrict__ gate, float* __restrict__ ao)
{
    extern __shared__ float sm[];
    float* Qs   = sm;                    // [64][AST]
    float* Ks   = Qs  + 64 * AST;        // [64][AST]
    float* Ssm  = Ks  + 64 * AST;        // [64][AST]
    float* Vs   = Ssm + 64 * AST;        // [64][VST]
    float* part = Vs  + 64 * VST;        // [4][64]
    float* rsum = part + 256;            // [64]

    const int tid  = threadIdx.x;
    const int warp = tid >> 5, lane = tid & 31;
    const int g    = lane >> 2, t = lane & 3;
    const int wm   = warp >> 2;          // 0..1
    const int wn   = warp & 3;           // 0..3
    const int sb   = blockIdx.x, bh = blockIdx.y;
    const int b    = bh / HEADS, h = bh % HEADS;
    const int s0   = sb * 64;

    if (tid < 64) rsum[tid] = 0.f;

#pragma unroll
    for (int l = 0; l < 4; l++) {
        int lin = tid + l * 256, r = lin >> 4, c4 = (lin & 15) << 2;
        float4 x = *(const float4*)&q[(size_t)(b * Ss + s0 + r) * Hh + h * KD + c4];
        float4 y = { to_tf32(x.x), to_tf32(x.y), to_tf32(x.z), to_tf32(x.w) };
        *(float4*)&Qs[r * AST + c4] = y;
    }

    float oacc[2][4][4];
#pragma unroll
    for (int mi = 0; mi < 2; mi++)
#pragma unroll
        for (int nj = 0; nj < 4; nj++)
#pragma unroll
            for (int r = 0; r < 4; r++) oacc[mi][nj][r] = 0.f;

    __syncthreads();

    const size_t mbase = (size_t)h * Ss * Ss;

    for (int tt = 0; tt <= sb; tt++) {
        const int t0 = tt * 64;

#pragma unroll
        for (int l = 0; l < 4; l++) {
            int lin = tid + l * 256, r = lin >> 4, c4 = (lin & 15) << 2;
            float4 x = *(const float4*)&k[(size_t)(b * Ss + t0 + r) * Hh + h * KD + c4];
            float4 y = { to_tf32(x.x), to_tf32(x.y), to_tf32(x.z), to_tf32(x.w) };
            *(float4*)&Ks[r * AST + c4] = y;
        }
#pragma unroll
        for (int l = 0; l < 8; l++) {
            int lin = tid + l * 256, r = lin >> 5, c4 = (lin & 31) << 2;
            float4 x = *(const float4*)&v[(size_t)(b * Ss + t0 + r) * VD + h * HD + c4];
            float4 y = { to_tf32(x.x), to_tf32(x.y), to_tf32(x.z), to_tf32(x.w) };
            *(float4*)&Vs[r * VST + c4] = y;
        }
        __syncthreads();

        float sacc[2][2][4];
#pragma unroll
        for (int mi = 0; mi < 2; mi++)
#pragma unroll
            for (int nj = 0; nj < 2; nj++)
#pragma unroll
                for (int r = 0; r < 4; r++) sacc[mi][nj][r] = 0.f;

#pragma unroll
        for (int ks = 0; ks < 8; ks++) {
            const int kb = ks * 8;
            unsigned af[2][4];
#pragma unroll
            for (int mi = 0; mi < 2; mi++) {
                int mb = wm * 32 + mi * 16 + g;
                af[mi][0] = __float_as_uint(Qs[(mb    ) * AST + kb + t    ]);
                af[mi][1] = __float_as_uint(Qs[(mb + 8) * AST + kb + t    ]);
                af[mi][2] = __float_as_uint(Qs[(mb    ) * AST + kb + t + 4]);
                af[mi][3] = __float_as_uint(Qs[(mb + 8) * AST + kb + t + 4]);
            }
            unsigned bf[2][2];
#pragma unroll
            for (int nj = 0; nj < 2; nj++) {
                int nb = wn * 16 + nj * 8 + g;
                bf[nj][0] = __float_as_uint(Ks[nb * AST + kb + t    ]);
                bf[nj][1] = __float_as_uint(Ks[nb * AST + kb + t + 4]);
            }
#pragma unroll
            for (int mi = 0; mi < 2; mi++)
#pragma unroll
                for (int nj = 0; nj < 2; nj++)
                    MMA_TF32(sacc[mi][nj], af[mi], bf[nj]);
        }

        float pr[2][2] = { {0.f, 0.f}, {0.f, 0.f} };
#pragma unroll
        for (int mi = 0; mi < 2; mi++) {
            int r0 = wm * 32 + mi * 16 + g;
#pragma unroll
            for (int nj = 0; nj < 2; nj++) {
                int col = wn * 16 + nj * 8 + 2 * t;
                float2 m0 = *(const float2*)&mask[mbase + (size_t)(s0 + r0    ) * Ss + t0 + col];
                float2 m1 = *(const float2*)&mask[mbase + (size_t)(s0 + r0 + 8) * Ss + t0 + col];
                float v0 = sacc[mi][nj][0] * m0.x;
                float v1 = sacc[mi][nj][1] * m0.y;
                float v2 = sacc[mi][nj][2] * m1.x;
                float v3 = sacc[mi][nj][3] * m1.y;
                pr[mi][0] += v0 + v1;
                pr[mi][1] += v2 + v3;
                float2 s01 = { to_tf32(v0), to_tf32(v1) };
                float2 s23 = { to_tf32(v2), to_tf32(v3) };
                *(float2*)&Ssm[(r0    ) * AST + col] = s01;
                *(float2*)&Ssm[(r0 + 8) * AST + col] = s23;
            }
        }
#pragma unroll
        for (int mi = 0; mi < 2; mi++)
#pragma unroll
            for (int rr = 0; rr < 2; rr++) {
                float p = pr[mi][rr];
                p += __shfl_xor_sync(0xffffffffu, p, 1);
                p += __shfl_xor_sync(0xffffffffu, p, 2);
                if (t == 0) part[wn * 64 + wm * 32 + mi * 16 + rr * 8 + g] = p;
            }
        __syncthreads();

        if (tid < 64)
            rsum[tid] += (part[tid] + part[64 + tid]) + (part[128 + tid] + part[192 + tid]);

#pragma unroll
        for (int ks = 0; ks < 8; ks++) {
            const int kb = ks * 8;
            unsigned af[2][4];
#pragma unroll
            for (int mi = 0; mi < 2; mi++) {
                int mb = wm * 32 + mi * 16 + g;
                af[mi][0] = __float_as_uint(Ssm[(mb    ) * AST + kb + t    ]);
                af[mi][1] = __float_as_uint(Ssm[(mb + 8) * AST + kb + t    ]);
                af[mi][2] = __float_as_uint(Ssm[(mb    ) * AST + kb + t + 4]);
                af[mi][3] = __float_as_uint(Ssm[(mb + 8) * AST + kb + t + 4]);
            }
            unsigned bf[4][2];
#pragma unroll
            for (int nj = 0; nj < 4; nj++) {
                int nb = wn * 32 + nj * 8 + g;
                bf[nj][0] = __float_as_uint(Vs[(kb + t    ) * VST + nb]);
                bf[nj][1] = __float_as_uint(Vs[(kb + t + 4) * VST + nb]);
            }
#pragma unroll
            for (int mi = 0; mi < 2; mi++)
#pragma unroll
                for (int nj = 0; nj < 4; nj++)
                    MMA_TF32(oacc[mi][nj], af[mi], bf[nj]);
        }
        __syncthreads();
    }

    // ---- epilogue: divide by rowsum, fused group-RMSnorm + SiLU gate ------
    float ssq[2][2] = { {0.f, 0.f}, {0.f, 0.f} };
#pragma unroll
    for (int mi = 0; mi < 2; mi++) {
        int r0 = wm * 32 + mi * 16 + g;
        float i0 = 1.f / fmaxf(fabsf(rsum[r0    ]), 1.f);
        float i1 = 1.f / fmaxf(fabsf(rsum[r0 + 8]), 1.f);
#pragma unroll
        for (int nj = 0; nj < 4; nj++) {
            oacc[mi][nj][0] *= i0;  oacc[mi][nj][1] *= i0;
            oacc[mi][nj][2] *= i1;  oacc[mi][nj][3] *= i1;
            ssq[mi][0] += oacc[mi][nj][0] * oacc[mi][nj][0]
                        + oacc[mi][nj][1] * oacc[mi][nj][1];
            ssq[mi][1] += oacc[mi][nj][2] * oacc[mi][nj][2]
                        + oacc[mi][nj][3] * oacc[mi][nj][3];
        }
    }
#pragma unroll
    for (int mi = 0; mi < 2; mi++)
#pragma unroll
        for (int rr = 0; rr < 2; rr++) {
            float p = ssq[mi][rr];
            p += __shfl_xor_sync(0xffffffffu, p, 1);
            p += __shfl_xor_sync(0xffffffffu, p, 2);
            if (t == 0) part[wn * 64 + wm * 32 + mi * 16 + rr * 8 + g] = p;
        }
    __syncthreads();

#pragma unroll
    for (int mi = 0; mi < 2; mi++) {
        int rl = wm * 32 + mi * 16 + g;
        float t0s = part[rl    ] + part[64 + rl    ] + part[128 + rl    ] + part[192 + rl    ];
        float t1s = part[rl + 8] + part[64 + rl + 8] + part[128 + rl + 8] + part[192 + rl + 8];
        float rms0 = rsqrtf(t0s * (1.f / 128.f) + 1e-5f);
        float rms1 = rsqrtf(t1s * (1.f / 128.f) + 1e-5f);
#pragma unroll
        for (int nj = 0; nj < 4; nj++) {
            int col = h * HD + wn * 32 + nj * 8 + 2 * t;
            size_t off0 = (size_t)(b * Ss + s0 + rl    ) * VD + col;
            size_t off1 = (size_t)(b * Ss + s0 + rl + 8) * VD + col;
            float2 gv0 = *(const float2*)&gate[off0];
            float2 gv1 = *(const float2*)&gate[off1];
            float2 o0, o1;
            o0.x = oacc[mi][nj][0] * rms0 * gv0.x * (1.f / (1.f + __expf(-gv0.x)));
            o0.y = oacc[mi][nj][1] * rms0 * gv0.y * (1.f / (1.f + __expf(-gv0.y)));
            o1.x = oacc[mi][nj][2] * rms1 * gv1.x * (1.f / (1.f + __expf(-gv1.x)));
            o1.y = oacc[mi][nj][3] * rms1 * gv1.y * (1.f / (1.f + __expf(-gv1.y)));
            *(float2*)&ao[off0] = o0;
            *(float2*)&ao[off1] = o1;
        }
    }
}

// ---------------- launcher -------------------------------------------------
extern "C" void kernel_launch(void* const* d_in, const int* in_sizes, int n_in,
                              void* d_out, int out_size)
{
    const float* x    = (const float*)d_in[0];
    const float* sn   = (const float*)d_in[1];
    const float* cs   = (const float*)d_in[2];
    const float* mask = (const float*)d_in[3];
    const float* Wq   = (const float*)d_in[4];
    const float* Wk   = (const float*)d_in[5];
    const float* Wv   = (const float*)d_in[6];
    const float* Wg   = (const float*)d_in[7];
    const float* Wo   = (const float*)d_in[8];
    float* out = (float*)d_out;

    float *q, *k, *v, *g, *ao;
    cudaGetSymbolAddress((void**)&q,  g_q);
    cudaGetSymbolAddress((void**)&k,  g_k);
    cudaGetSymbolAddress((void**)&v,  g_v);
    cudaGetSymbolAddress((void**)&g,  g_g);
    cudaGetSymbolAddress((void**)&ao, g_ao);

    const int attn_smem = (3 * 64 * AST + 64 * VST + 256 + 64) * (int)sizeof(float);
    cudaFuncSetAttribute(attn_tc, cudaFuncAttributeMaxDynamicSharedMemorySize,
                         attn_smem);

    proj_qkvg<<<dim3(48, 32), 256>>>(x, Wq, Wk, Wv, Wg, sn, cs, q, k, v, g);

    attn_tc<<<dim3(Ss / 64, Bb * HEADS), 256, attn_smem>>>(q, k, v, mask, g, ao);

    gemm_out<<<dim3(8, 32), 256>>>(ao, Wo, out);
}

// round 11
// speedup vs baseline: 3.5312x; 1.0496x over previous
#include <cuda_runtime.h>

#define Bb 2
#define Ss 2048
#define Hh 1024
#define HEADS 16
#define KD 64
#define VD 2048
#define HD 128
#define MS (Bb*Ss)   /* 4096 rows */

// ---------------- scratch (device globals; no allocation allowed) ----------
__device__ float g_q [MS*Hh];
__device__ float g_k [MS*Hh];
__device__ float g_v [MS*VD];
__device__ float g_g [MS*VD];
__device__ float g_ao[MS*VD];

// ---------------- helpers --------------------------------------------------
__device__ __forceinline__ float to_tf32(float x) {
    unsigned u;
    asm("cvt.rna.tf32.f32 %0, %1;" : "=r"(u) : "f"(x));
    return __uint_as_float(u);
}
__device__ __forceinline__ unsigned tf32b(unsigned u) {
    unsigned r;
    asm("cvt.rna.tf32.f32 %0, %1;" : "=r"(r) : "f"(__uint_as_float(u)));
    return r;
}

#define MMA_TF32(c, a, b)                                                     \
    asm volatile(                                                             \
        "mma.sync.aligned.m16n8k8.row.col.f32.tf32.tf32.f32 "                 \
        "{%0,%1,%2,%3}, {%4,%5,%6,%7}, {%8,%9}, {%0,%1,%2,%3};"               \
        : "+f"((c)[0]), "+f"((c)[1]), "+f"((c)[2]), "+f"((c)[3])              \
        : "r"((a)[0]), "r"((a)[1]), "r"((a)[2]), "r"((a)[3]),                 \
          "r"((b)[0]), "r"((b)[1]))

__device__ __forceinline__ void ldsm4(unsigned r[4], unsigned addr) {
    asm volatile("ldmatrix.sync.aligned.m8n8.x4.shared.b16 {%0,%1,%2,%3}, [%4];"
                 : "=r"(r[0]), "=r"(r[1]), "=r"(r[2]), "=r"(r[3]) : "r"(addr));
}
__device__ __forceinline__ void cp16(unsigned saddr, const void* gaddr) {
    asm volatile("cp.async.cg.shared.global [%0], [%1], 16;"
                 :: "r"(saddr), "l"(gaddr));
}
#define CP_COMMIT() asm volatile("cp.async.commit_group;")
#define CP_WAIT1()  asm volatile("cp.async.wait_group 1;")

// ============================================================================
// Core 128x128 tf32 GEMM body: C = alpha * A(MxK) * B(NxK)^T, optional rope.
// 128 threads, 4 warps, warp tile 64x64. cp.async 3-stage pipeline.
// Smem tile: [128 m][16 k] floats as float4 chunks, chunk' = k4 ^ ((m>>1)&3).
// tf32 cvt.rna applied on fragments post-ldmatrix (numerically identical to
// cvt-at-store). Conflict-free stores (8-lane phases cover 8 distinct chunks
// in one 128B line-pair) and ldmatrix phases (proven in R7/R8).
// ============================================================================
__device__ __forceinline__ void gemm128_body(
    const float* __restrict__ A, const float* __restrict__ Bm,
    float* __restrict__ C, int N, int K, float alpha,
    int m0, int n0, bool rope,
    const float* __restrict__ sn, const float* __restrict__ cs,
    float* As, float* Bs)
{
    const int tid  = threadIdx.x;
    const int warp = tid >> 5, lane = tid & 31;
    const int g    = lane >> 2, t = lane & 3;
    const int wm   = warp >> 1;      // 0..1
    const int wn   = warp & 1;       // 0..1
    const int row0 = tid >> 2;       // 0..31
    const int k4   = tid & 3;        // chunk 0..3

    float acc[4][8][4];
#pragma unroll
    for (int i = 0; i < 4; i++)
#pragma unroll
        for (int j = 0; j < 8; j++)
#pragma unroll
            for (int r = 0; r < 4; r++) acc[i][j][r] = 0.f;

    const float* Ag = A  + (size_t)(m0 + row0) * K + k4 * 4;
    const float* Bg = Bm + (size_t)(n0 + row0) * K + k4 * 4;
    const size_t rstep = (size_t)32 * K;

    const unsigned aSb = (unsigned)__cvta_generic_to_shared(As);
    const unsigned bSb = (unsigned)__cvta_generic_to_shared(Bs);

    // cp.async smem byte targets for the 4 row-groups (stage-relative)
    unsigned sA[4], sB[4];
#pragma unroll
    for (int r = 0; r < 4; r++) {
        int rr  = row0 + r * 32;
        int idx = rr * 4 + (k4 ^ ((rr >> 1) & 3));
        sA[r] = aSb + idx * 16;
        sB[r] = bSb + idx * 16;
    }

    // ldmatrix per-lane address precompute
    const int sel = lane >> 3;
    unsigned a_off[4]; int a_sw[4];
#pragma unroll
    for (int mi = 0; mi < 4; mi++) {
        int mr = wm * 64 + mi * 16 + (sel & 1) * 8 + (lane & 7);
        a_sw[mi]  = (mr >> 1) & 3;
        a_off[mi] = aSb + mr * 64;
    }
    const int dkA = sel >> 1;
    unsigned b_off[4]; int b_sw[4];
#pragma unroll
    for (int p = 0; p < 4; p++) {
        int nr = wn * 64 + p * 16 + (sel >> 1) * 8 + (lane & 7);
        b_sw[p]  = (nr >> 1) & 3;
        b_off[p] = bSb + nr * 64;
    }
    const int dkB = sel & 1;

    const int NIT = K / 16;

    // prologue: stages 0,1
#pragma unroll
    for (int st = 0; st < 2; st++) {
        const float* Agn = Ag + st * 16;
        const float* Bgn = Bg + st * 16;
#pragma unroll
        for (int r = 0; r < 4; r++) {
            cp16(sA[r] + st * 8192, Agn + r * rstep);
            cp16(sB[r] + st * 8192, Bgn + r * rstep);
        }
        CP_COMMIT();
    }

    int stage = 0;
    for (int it = 0; it < NIT; ++it) {
        CP_WAIT1();
        __syncthreads();

        const int inext = it + 2;
        if (inext < NIT) {
            const unsigned so = (unsigned)((inext % 3) * 8192);
            const float* Agn = Ag + inext * 16;
            const float* Bgn = Bg + inext * 16;
#pragma unroll
            for (int r = 0; r < 4; r++) {
                cp16(sA[r] + so, Agn + r * rstep);
                cp16(sB[r] + so, Bgn + r * rstep);
            }
        }
        CP_COMMIT();

        const unsigned so = (unsigned)(stage * 8192);
#pragma unroll
        for (int ks = 0; ks < 2; ks++) {
            const int ks2 = ks * 2;
            unsigned af[4][4];
#pragma unroll
            for (int mi = 0; mi < 4; mi++) {
                ldsm4(af[mi], a_off[mi] + so + (((ks2 + dkA) ^ a_sw[mi]) << 4));
#pragma unroll
                for (int j = 0; j < 4; j++) af[mi][j] = tf32b(af[mi][j]);
            }
            unsigned bf[4][4];
#pragma unroll
            for (int p = 0; p < 4; p++) {
                ldsm4(bf[p], b_off[p] + so + (((ks2 + dkB) ^ b_sw[p]) << 4));
#pragma unroll
                for (int j = 0; j < 4; j++) bf[p][j] = tf32b(bf[p][j]);
            }
#pragma unroll
            for (int mi = 0; mi < 4; mi++)
#pragma unroll
                for (int nj = 0; nj < 8; nj++)
                    MMA_TF32(acc[mi][nj], af[mi], &bf[nj >> 1][(nj & 1) * 2]);
        }
        stage = (stage == 2) ? 0 : stage + 1;
    }

    // ---- epilogue (optional fused rotary for q/k segments) -----------------
#pragma unroll
    for (int mi = 0; mi < 4; mi++) {
        int r0  = m0 + wm * 64 + mi * 16 + g;
        int sA_ = r0 & (Ss - 1);
        int sB_ = (r0 + 8) & (Ss - 1);
#pragma unroll
        for (int nj = 0; nj < 8; nj++) {
            int col = n0 + wn * 64 + nj * 8 + 2 * t;
            float e0 = alpha * acc[mi][nj][0];
            float o0 = alpha * acc[mi][nj][1];
            float e1 = alpha * acc[mi][nj][2];
            float o1 = alpha * acc[mi][nj][3];
            if (rope) {
                int hc = col & 63;
                float2 cA = *(const float2*)&cs[sA_ * KD + hc];
                float2 sAv= *(const float2*)&sn[sA_ * KD + hc];
                float2 cB = *(const float2*)&cs[sB_ * KD + hc];
                float2 sBv= *(const float2*)&sn[sB_ * KD + hc];
                float ne0 = e0 * cA.x - o0 * sAv.x;
                float no0 = o0 * cA.y + e0 * sAv.y;
                float ne1 = e1 * cB.x - o1 * sBv.x;
                float no1 = o1 * cB.y + e1 * sBv.y;
                e0 = ne0; o0 = no0; e1 = ne1; o1 = no1;
            }
            float2 w01 = { e0, o0 };
            float2 w23 = { e1, o1 };
            *(float2*)&C[(size_t)r0 * N + col]       = w01;
            *(float2*)&C[(size_t)(r0 + 8) * N + col] = w23;
        }
    }
}

// ---------------- fused Q/K/V/G projections (+rope on q,k) -----------------
__global__ __launch_bounds__(128, 2)
void proj_qkvg(const float* __restrict__ x,
               const float* __restrict__ Wq, const float* __restrict__ Wk,
               const float* __restrict__ Wv, const float* __restrict__ Wg,
               const float* __restrict__ sn, const float* __restrict__ cs,
               float* __restrict__ q, float* __restrict__ k,
               float* __restrict__ v, float* __restrict__ g)
{
    __shared__ float As[3 * 2048];
    __shared__ float Bs[3 * 2048];
    const int bx = blockIdx.x;
    const float* Bm; float* Cp; int Nloc; float alpha; bool rope; int nb;
    if (bx < 8)       { Bm = Wq; Cp = q; Nloc = 1024; alpha = 1.f;    rope = true;  nb = bx; }
    else if (bx < 16) { Bm = Wk; Cp = k; Nloc = 1024; alpha = 0.125f; rope = true;  nb = bx - 8; }
    else if (bx < 32) { Bm = Wv; Cp = v; Nloc = 2048; alpha = 1.f;    rope = false; nb = bx - 16; }
    else              { Bm = Wg; Cp = g; Nloc = 2048; alpha = 1.f;    rope = false; nb = bx - 32; }
    gemm128_body(x, Bm, Cp, Nloc, Hh, alpha, blockIdx.y * 128, nb * 128,
                 rope, sn, cs, As, Bs);
}

// ---------------- output projection ----------------------------------------
__global__ __launch_bounds__(128, 2)
void gemm_out(const float* __restrict__ A, const float* __restrict__ Bm,
              float* __restrict__ C)
{
    __shared__ float As[3 * 2048];
    __shared__ float Bs[3 * 2048];
    gemm128_body(A, Bm, C, Hh, VD, 1.f, blockIdx.y * 128, blockIdx.x * 128,
                 false, nullptr, nullptr, As, Bs);
}

// ---------------- retention attention (tf32 TC) + fused gnorm/gate ---------
#define AST 68
#define VST 136
__global__ __launch_bounds__(256, 2)
void attn_tc(const float* __restrict__ q, const float* __restrict__ k,
             const float* __restrict__ v, const float* __restrict__ mask,
             const float* __restrict__ gate, float* __restrict__ ao)
{
    extern __shared__ float sm[];
    float* Qs   = sm;                    // [64][AST]
    float* Ks   = Qs  + 64 * AST;        // [64][AST]
    float* Ssm  = Ks  + 64 * AST;        // [64][AST]
    float* Vs   = Ssm + 64 * AST;        // [64][VST]
    float* part = Vs  + 64 * VST;        // [4][64]
    float* rsum = part + 256;            // [64]

    const int tid  = threadIdx.x;
    const int warp = tid >> 5, lane = tid & 31;
    const int g    = lane >> 2, t = lane & 3;
    const int wm   = warp >> 2;          // 0..1
    const int wn   = warp & 3;           // 0..3
    const int sb   = blockIdx.x, bh = blockIdx.y;
    const int b    = bh / HEADS, h = bh % HEADS;
    const int s0   = sb * 64;

    if (tid < 64) rsum[tid] = 0.f;

#pragma unroll
    for (int l = 0; l < 4; l++) {
        int lin = tid + l * 256, r = lin >> 4, c4 = (lin & 15) << 2;
        float4 x = *(const float4*)&q[(size_t)(b * Ss + s0 + r) * Hh + h * KD + c4];
        float4 y = { to_tf32(x.x), to_tf32(x.y), to_tf32(x.z), to_tf32(x.w) };
        *(float4*)&Qs[r * AST + c4] = y;
    }

    float oacc[2][4][4];
#pragma unroll
    for (int mi = 0; mi < 2; mi++)
#pragma unroll
        for (int nj = 0; nj < 4; nj++)
#pragma unroll
            for (int r = 0; r < 4; r++) oacc[mi][nj][r] = 0.f;

    __syncthreads();

    const size_t mbase = (size_t)h * Ss * Ss;

    for (int tt = 0; tt <= sb; tt++) {
        const int t0 = tt * 64;

#pragma unroll
        for (int l = 0; l < 4; l++) {
            int lin = tid + l * 256, r = lin >> 4, c4 = (lin & 15) << 2;
            float4 x = *(const float4*)&k[(size_t)(b * Ss + t0 + r) * Hh + h * KD + c4];
            float4 y = { to_tf32(x.x), to_tf32(x.y), to_tf32(x.z), to_tf32(x.w) };
            *(float4*)&Ks[r * AST + c4] = y;
        }
#pragma unroll
        for (int l = 0; l < 8; l++) {
            int lin = tid + l * 256, r = lin >> 5, c4 = (lin & 31) << 2;
            float4 x = *(const float4*)&v[(size_t)(b * Ss + t0 + r) * VD + h * HD + c4];
            float4 y = { to_tf32(x.x), to_tf32(x.y), to_tf32(x.z), to_tf32(x.w) };
            *(float4*)&Vs[r * VST + c4] = y;
        }
        __syncthreads();

        float sacc[2][2][4];
#pragma unroll
        for (int mi = 0; mi < 2; mi++)
#pragma unroll
            for (int nj = 0; nj < 2; nj++)
#pragma unroll
                for (int r = 0; r < 4; r++) sacc[mi][nj][r] = 0.f;

#pragma unroll
        for (int ks = 0; ks < 8; ks++) {
            const int kb = ks * 8;
            unsigned af[2][4];
#pragma unroll
            for (int mi = 0; mi < 2; mi++) {
                int mb = wm * 32 + mi * 16 + g;
                af[mi][0] = __float_as_uint(Qs[(mb    ) * AST + kb + t    ]);
                af[mi][1] = __float_as_uint(Qs[(mb + 8) * AST + kb + t    ]);
                af[mi][2] = __float_as_uint(Qs[(mb    ) * AST + kb + t + 4]);
                af[mi][3] = __float_as_uint(Qs[(mb + 8) * AST + kb + t + 4]);
            }
            unsigned bf[2][2];
#pragma unroll
            for (int nj = 0; nj < 2; nj++) {
                int nb = wn * 16 + nj * 8 + g;
                bf[nj][0] = __float_as_uint(Ks[nb * AST + kb + t    ]);
                bf[nj][1] = __float_as_uint(Ks[nb * AST + kb + t + 4]);
            }
#pragma unroll
            for (int mi = 0; mi < 2; mi++)
#pragma unroll
                for (int nj = 0; nj < 2; nj++)
                    MMA_TF32(sacc[mi][nj], af[mi], bf[nj]);
        }

        float pr[2][2] = { {0.f, 0.f}, {0.f, 0.f} };
#pragma unroll
        for (int mi = 0; mi < 2; mi++) {
            int r0 = wm * 32 + mi * 16 + g;
#pragma unroll
            for (int nj = 0; nj < 2; nj++) {
                int col = wn * 16 + nj * 8 + 2 * t;
                float2 m0 = *(const float2*)&mask[mbase + (size_t)(s0 + r0    ) * Ss + t0 + col];
                float2 m1 = *(const float2*)&mask[mbase + (size_t)(s0 + r0 + 8) * Ss + t0 + col];
                float v0 = sacc[mi][nj][0] * m0.x;
                float v1 = sacc[mi][nj][1] * m0.y;
                float v2 = sacc[mi][nj][2] * m1.x;
                float v3 = sacc[mi][nj][3] * m1.y;
                pr[mi][0] += v0 + v1;
                pr[mi][1] += v2 + v3;
                float2 s01 = { to_tf32(v0), to_tf32(v1) };
                float2 s23 = { to_tf32(v2), to_tf32(v3) };
                *(float2*)&Ssm[(r0    ) * AST + col] = s01;
                *(float2*)&Ssm[(r0 + 8) * AST + col] = s23;
            }
        }
#pragma unroll
        for (int mi = 0; mi < 2; mi++)
#pragma unroll
            for (int rr = 0; rr < 2; rr++) {
                float p = pr[mi][rr];
                p += __shfl_xor_sync(0xffffffffu, p, 1);
                p += __shfl_xor_sync(0xffffffffu, p, 2);
                if (t == 0) part[wn * 64 + wm * 32 + mi * 16 + rr * 8 + g] = p;
            }
        __syncthreads();

        if (tid < 64)
            rsum[tid] += (part[tid] + part[64 + tid]) + (part[128 + tid] + part[192 + tid]);

#pragma unroll
        for (int ks = 0; ks < 8; ks++) {
            const int kb = ks * 8;
            unsigned af[2][4];
#pragma unroll
            for (int mi = 0; mi < 2; mi++) {
                int mb = wm * 32 + mi * 16 + g;
                af[mi][0] = __float_as_uint(Ssm[(mb    ) * AST + kb + t    ]);
                af[mi][1] = __float_as_uint(Ssm[(mb + 8) * AST + kb + t    ]);
                af[mi][2] = __float_as_uint(Ssm[(mb    ) * AST + kb + t + 4]);
                af[mi][3] = __float_as_uint(Ssm[(mb + 8) * AST + kb + t + 4]);
            }
            unsigned bf[4][2];
#pragma unroll
            for (int nj = 0; nj < 4; nj++) {
                int nb = wn * 32 + nj * 8 + g;
                bf[nj][0] = __float_as_uint(Vs[(kb + t    ) * VST + nb]);
                bf[nj][1] = __float_as_uint(Vs[(kb + t + 4) * VST + nb]);
            }
#pragma unroll
            for (int mi = 0; mi < 2; mi++)
#pragma unroll
                for (int nj = 0; nj < 4; nj++)
                    MMA_TF32(oacc[mi][nj], af[mi], bf[nj]);
        }
        __syncthreads();
    }

    // ---- epilogue: divide by rowsum, fused group-RMSnorm + SiLU gate ------
    float ssq[2][2] = { {0.f, 0.f}, {0.f, 0.f} };
#pragma unroll
    for (int mi = 0; mi < 2; mi++) {
        int r0 = wm * 32 + mi * 16 + g;
        float i0 = 1.f / fmaxf(fabsf(rsum[r0    ]), 1.f);
        float i1 = 1.f / fmaxf(fabsf(rsum[r0 + 8]), 1.f);
#pragma unroll
        for (int nj = 0; nj < 4; nj++) {
            oacc[mi][nj][0] *= i0;  oacc[mi][nj][1] *= i0;
            oacc[mi][nj][2] *= i1;  oacc[mi][nj][3] *= i1;
            ssq[mi][0] += oacc[mi][nj][0] * oacc[mi][nj][0]
                        + oacc[mi][nj][1] * oacc[mi][nj][1];
            ssq[mi][1] += oacc[mi][nj][2] * oacc[mi][nj][2]
                        + oacc[mi][nj][3] * oacc[mi][nj][3];
        }
    }
#pragma unroll
    for (int mi = 0; mi < 2; mi++)
#pragma unroll
        for (int rr = 0; rr < 2; rr++) {
            float p = ssq[mi][rr];
            p += __shfl_xor_sync(0xffffffffu, p, 1);
            p += __shfl_xor_sync(0xffffffffu, p, 2);
            if (t == 0) part[wn * 64 + wm * 32 + mi * 16 + rr * 8 + g] = p;
        }
    __syncthreads();

#pragma unroll
    for (int mi = 0; mi < 2; mi++) {
        int rl = wm * 32 + mi * 16 + g;
        float t0s = part[rl    ] + part[64 + rl    ] + part[128 + rl    ] + part[192 + rl    ];
        float t1s = part[rl + 8] + part[64 + rl + 8] + part[128 + rl + 8] + part[192 + rl + 8];
        float rms0 = rsqrtf(t0s * (1.f / 128.f) + 1e-5f);
        float rms1 = rsqrtf(t1s * (1.f / 128.f) + 1e-5f);
#pragma unroll
        for (int nj = 0; nj < 4; nj++) {
            int col = h * HD + wn * 32 + nj * 8 + 2 * t;
            size_t off0 = (size_t)(b * Ss + s0 + rl    ) * VD + col;
            size_t off1 = (size_t)(b * Ss + s0 + rl + 8) * VD + col;
            float2 gv0 = *(const float2*)&gate[off0];
            float2 gv1 = *(const float2*)&gate[off1];
            float2 o0, o1;
            o0.x = oacc[mi][nj][0] * rms0 * gv0.x * (1.f / (1.f + __expf(-gv0.x)));
            o0.y = oacc[mi][nj][1] * rms0 * gv0.y * (1.f / (1.f + __expf(-gv0.y)));
            o1.x = oacc[mi][nj][2] * rms1 * gv1.x * (1.f / (1.f + __expf(-gv1.x)));
            o1.y = oacc[mi][nj][3] * rms1 * gv1.y * (1.f / (1.f + __expf(-gv1.y)));
            *(float2*)&ao[off0] = o0;
            *(float2*)&ao[off1] = o1;
        }
    }
}

// ---------------- launcher -------------------------------------------------
extern "C" void kernel_launch(void* const* d_in, const int* in_sizes, int n_in,
                              void* d_out, int out_size)
{
    const float* x    = (const float*)d_in[0];
    const float* sn   = (const float*)d_in[1];
    const float* cs   = (const float*)d_in[2];
    const float* mask = (const float*)d_in[3];
    const float* Wq   = (const float*)d_in[4];
    const float* Wk   = (const float*)d_in[5];
    const float* Wv   = (const float*)d_in[6];
    const float* Wg   = (const float*)d_in[7];
    const float* Wo   = (const float*)d_in[8];
    float* out = (float*)d_out;

    float *q, *k, *v, *g, *ao;
    cudaGetSymbolAddress((void**)&q,  g_q);
    cudaGetSymbolAddress((void**)&k,  g_k);
    cudaGetSymbolAddress((void**)&v,  g_v);
    cudaGetSymbolAddress((void**)&g,  g_g);
    cudaGetSymbolAddress((void**)&ao, g_ao);

    const int attn_smem = (3 * 64 * AST + 64 * VST + 256 + 64) * (int)sizeof(float);
    cudaFuncSetAttribute(attn_tc, cudaFuncAttributeMaxDynamicSharedMemorySize,
                         attn_smem);

    proj_qkvg<<<dim3(48, 32), 128>>>(x, Wq, Wk, Wv, Wg, sn, cs, q, k, v, g);

    attn_tc<<<dim3(Ss / 64, Bb * HEADS), 256, attn_smem>>>(q, k, v, mask, g, ao);

    gemm_out<<<dim3(8, 32), 128>>>(ao, Wo, out);
}

// round 12
// speedup vs baseline: 3.9473x; 1.1178x over previous
#include <cuda_runtime.h>

#define Bb 2
#define Ss 2048
#define Hh 1024
#define HEADS 16
#define KD 64
#define VD 2048
#define HD 128
#define MS (Bb*Ss)   /* 4096 rows */

// ---------------- scratch (device globals; no allocation allowed) ----------
__device__ float g_q [MS*Hh];
__device__ float g_k [MS*Hh];
__device__ float g_v [MS*VD];
__device__ float g_g [MS*VD];
__device__ float g_ao[MS*VD];
__device__ float g_xr[MS*Hh];          // tf32-rounded x
__device__ float g_wr[8*1024*1024];    // tf32-rounded Wq|Wk|Wv|Wg|Wo

// ---------------- helpers --------------------------------------------------
__device__ __forceinline__ float to_tf32(float x) {
    unsigned u;
    asm("cvt.rna.tf32.f32 %0, %1;" : "=r"(u) : "f"(x));
    return __uint_as_float(u);
}

#define MMA_TF32(c, a, b)                                                     \
    asm volatile(                                                             \
        "mma.sync.aligned.m16n8k8.row.col.f32.tf32.tf32.f32 "                 \
        "{%0,%1,%2,%3}, {%4,%5,%6,%7}, {%8,%9}, {%0,%1,%2,%3};"               \
        : "+f"((c)[0]), "+f"((c)[1]), "+f"((c)[2]), "+f"((c)[3])              \
        : "r"((a)[0]), "r"((a)[1]), "r"((a)[2]), "r"((a)[3]),                 \
          "r"((b)[0]), "r"((b)[1]))

__device__ __forceinline__ void ldsm4(unsigned r[4], unsigned addr) {
    asm volatile("ldmatrix.sync.aligned.m8n8.x4.shared.b16 {%0,%1,%2,%3}, [%4];"
                 : "=r"(r[0]), "=r"(r[1]), "=r"(r[2]), "=r"(r[3]) : "r"(addr));
}
__device__ __forceinline__ void cp16(unsigned saddr, const void* gaddr) {
    asm volatile("cp.async.cg.shared.global [%0], [%1], 16;"
                 :: "r"(saddr), "l"(gaddr));
}
#define CP_COMMIT() asm volatile("cp.async.commit_group;")
#define CP_WAIT1()  asm volatile("cp.async.wait_group 1;")

// ---------------- producer-side tf32 rounding pass --------------------------
// segments (float4 units): x 1048576 | wq 262144 | wk 262144 | wv 524288 |
//                          wg 524288 | wo 524288  -> total 3145728
__global__ __launch_bounds__(256)
void pre_round(const float4* __restrict__ x,  const float4* __restrict__ wq,
               const float4* __restrict__ wk, const float4* __restrict__ wv,
               const float4* __restrict__ wg, const float4* __restrict__ wo,
               float4* __restrict__ xr, float4* __restrict__ wr)
{
    int i = blockIdx.x * blockDim.x + threadIdx.x;
    const float4* src; float4* dst; int off;
    if (i < 1048576)      { src = x;  dst = xr;            off = i; }
    else if (i < 1310720) { src = wq; dst = wr;            off = i - 1048576; }
    else if (i < 1572864) { src = wk; dst = wr + 262144;   off = i - 1310720; }
    else if (i < 2097152) { src = wv; dst = wr + 524288;   off = i - 1572864; }
    else if (i < 2621440) { src = wg; dst = wr + 1048576;  off = i - 2097152; }
    else                  { src = wo; dst = wr + 1572864;  off = i - 2621440; }
    float4 a = src[off];
    dst[off] = make_float4(to_tf32(a.x), to_tf32(a.y), to_tf32(a.z), to_tf32(a.w));
}

// ============================================================================
// Core 128x128 tf32 GEMM body: C = alpha * A(MxK) * B(NxK)^T, optional rope.
// 128 threads, 4 warps, warp tile 64x64. cp.async 3-stage pipeline.
// Inputs are PRE-ROUNDED to tf32 -> no cvt in the hot loop.
// Smem tile: [128 m][16 k] floats as float4 chunks, chunk' = k4 ^ ((m>>1)&3).
// outRound: store C values tf32-rounded (for MMA-consumed outputs).
// ============================================================================
__device__ __forceinline__ void gemm128_body(
    const float* __restrict__ A, const float* __restrict__ Bm,
    float* __restrict__ C, int N, int K, float alpha,
    int m0, int n0, bool rope, bool outRound,
    const float* __restrict__ sn, const float* __restrict__ cs,
    float* As, float* Bs)
{
    const int tid  = threadIdx.x;
    const int warp = tid >> 5, lane = tid & 31;
    const int g    = lane >> 2, t = lane & 3;
    const int wm   = warp >> 1;      // 0..1
    const int wn   = warp & 1;       // 0..1
    const int row0 = tid >> 2;       // 0..31
    const int k4   = tid & 3;        // chunk 0..3

    float acc[4][8][4];
#pragma unroll
    for (int i = 0; i < 4; i++)
#pragma unroll
        for (int j = 0; j < 8; j++)
#pragma unroll
            for (int r = 0; r < 4; r++) acc[i][j][r] = 0.f;

    const float* Ag = A  + (size_t)(m0 + row0) * K + k4 * 4;
    const float* Bg = Bm + (size_t)(n0 + row0) * K + k4 * 4;
    const size_t rstep = (size_t)32 * K;

    const unsigned aSb = (unsigned)__cvta_generic_to_shared(As);
    const unsigned bSb = (unsigned)__cvta_generic_to_shared(Bs);

    unsigned sA[4], sB[4];
#pragma unroll
    for (int r = 0; r < 4; r++) {
        int rr  = row0 + r * 32;
        int idx = rr * 4 + (k4 ^ ((rr >> 1) & 3));
        sA[r] = aSb + idx * 16;
        sB[r] = bSb + idx * 16;
    }

    const int sel = lane >> 3;
    unsigned a_off[4]; int a_sw[4];
#pragma unroll
    for (int mi = 0; mi < 4; mi++) {
        int mr = wm * 64 + mi * 16 + (sel & 1) * 8 + (lane & 7);
        a_sw[mi]  = (mr >> 1) & 3;
        a_off[mi] = aSb + mr * 64;
    }
    const int dkA = sel >> 1;
    unsigned b_off[4]; int b_sw[4];
#pragma unroll
    for (int p = 0; p < 4; p++) {
        int nr = wn * 64 + p * 16 + (sel >> 1) * 8 + (lane & 7);
        b_sw[p]  = (nr >> 1) & 3;
        b_off[p] = bSb + nr * 64;
    }
    const int dkB = sel & 1;

    const int NIT = K / 16;

#pragma unroll
    for (int st = 0; st < 2; st++) {
        const float* Agn = Ag + st * 16;
        const float* Bgn = Bg + st * 16;
#pragma unroll
        for (int r = 0; r < 4; r++) {
            cp16(sA[r] + st * 8192, Agn + r * rstep);
            cp16(sB[r] + st * 8192, Bgn + r * rstep);
        }
        CP_COMMIT();
    }

    int stage = 0;
    for (int it = 0; it < NIT; ++it) {
        CP_WAIT1();
        __syncthreads();

        const int inext = it + 2;
        if (inext < NIT) {
            const unsigned so = (unsigned)((inext % 3) * 8192);
            const float* Agn = Ag + inext * 16;
            const float* Bgn = Bg + inext * 16;
#pragma unroll
            for (int r = 0; r < 4; r++) {
                cp16(sA[r] + so, Agn + r * rstep);
                cp16(sB[r] + so, Bgn + r * rstep);
            }
        }
        CP_COMMIT();

        const unsigned so = (unsigned)(stage * 8192);
#pragma unroll
        for (int ks = 0; ks < 2; ks++) {
            const int ks2 = ks * 2;
            unsigned af[4][4];
#pragma unroll
            for (int mi = 0; mi < 4; mi++)
                ldsm4(af[mi], a_off[mi] + so + (((ks2 + dkA) ^ a_sw[mi]) << 4));
            unsigned bf[4][4];
#pragma unroll
            for (int p = 0; p < 4; p++)
                ldsm4(bf[p], b_off[p] + so + (((ks2 + dkB) ^ b_sw[p]) << 4));
#pragma unroll
            for (int mi = 0; mi < 4; mi++)
#pragma unroll
                for (int nj = 0; nj < 8; nj++)
                    MMA_TF32(acc[mi][nj], af[mi], &bf[nj >> 1][(nj & 1) * 2]);
        }
        stage = (stage == 2) ? 0 : stage + 1;
    }

    // ---- epilogue (optional fused rotary; optional tf32-rounded store) ----
#pragma unroll
    for (int mi = 0; mi < 4; mi++) {
        int r0  = m0 + wm * 64 + mi * 16 + g;
        int sA_ = r0 & (Ss - 1);
        int sB_ = (r0 + 8) & (Ss - 1);
#pragma unroll
        for (int nj = 0; nj < 8; nj++) {
            int col = n0 + wn * 64 + nj * 8 + 2 * t;
            float e0 = alpha * acc[mi][nj][0];
            float o0 = alpha * acc[mi][nj][1];
            float e1 = alpha * acc[mi][nj][2];
            float o1 = alpha * acc[mi][nj][3];
            if (rope) {
                int hc = col & 63;
                float2 cA = *(const float2*)&cs[sA_ * KD + hc];
                float2 sAv= *(const float2*)&sn[sA_ * KD + hc];
                float2 cB = *(const float2*)&cs[sB_ * KD + hc];
                float2 sBv= *(const float2*)&sn[sB_ * KD + hc];
                float ne0 = e0 * cA.x - o0 * sAv.x;
                float no0 = o0 * cA.y + e0 * sAv.y;
                float ne1 = e1 * cB.x - o1 * sBv.x;
                float no1 = o1 * cB.y + e1 * sBv.y;
                e0 = ne0; o0 = no0; e1 = ne1; o1 = no1;
            }
            if (outRound) {
                e0 = to_tf32(e0); o0 = to_tf32(o0);
                e1 = to_tf32(e1); o1 = to_tf32(o1);
            }
            float2 w01 = { e0, o0 };
            float2 w23 = { e1, o1 };
            *(float2*)&C[(size_t)r0 * N + col]       = w01;
            *(float2*)&C[(size_t)(r0 + 8) * N + col] = w23;
        }
    }
}

// ---------------- fused Q/K/V/G projections (+rope on q,k) -----------------
__global__ __launch_bounds__(128, 2)
void proj_qkvg(const float* __restrict__ x, const float* __restrict__ wr,
               const float* __restrict__ sn, const float* __restrict__ cs,
               float* __restrict__ q, float* __restrict__ k,
               float* __restrict__ v, float* __restrict__ g)
{
    __shared__ float As[3 * 2048];
    __shared__ float Bs[3 * 2048];
    const int bx = blockIdx.x;
    const float* Bm; float* Cp; int Nloc; float alpha; bool rope, orn; int nb;
    if (bx < 8)       { Bm = wr;           Cp = q; Nloc = 1024; alpha = 1.f;    rope = true;  orn = true;  nb = bx; }
    else if (bx < 16) { Bm = wr + 1048576; Cp = k; Nloc = 1024; alpha = 0.125f; rope = true;  orn = true;  nb = bx - 8; }
    else if (bx < 32) { Bm = wr + 2097152; Cp = v; Nloc = 2048; alpha = 1.f;    rope = false; orn = true;  nb = bx - 16; }
    else              { Bm = wr + 4194304; Cp = g; Nloc = 2048; alpha = 1.f;    rope = false; orn = false; nb = bx - 32; }
    gemm128_body(x, Bm, Cp, Nloc, Hh, alpha, blockIdx.y * 128, nb * 128,
                 rope, orn, sn, cs, As, Bs);
}

// ---------------- output projection ----------------------------------------
__global__ __launch_bounds__(128, 2)
void gemm_out(const float* __restrict__ A, const float* __restrict__ Bm,
              float* __restrict__ C)
{
    __shared__ float As[3 * 2048];
    __shared__ float Bs[3 * 2048];
    gemm128_body(A, Bm, C, Hh, VD, 1.f, blockIdx.y * 128, blockIdx.x * 128,
                 false, false, nullptr, nullptr, As, Bs);
}

// ---------------- retention attention (tf32 TC) + fused gnorm/gate ---------
// q/k/v arrive pre-rounded to tf32; smem fills are plain copies.
#define AST 68
#define VST 136
__global__ __launch_bounds__(256, 2)
void attn_tc(const float* __restrict__ q, const float* __restrict__ k,
             const float* __restrict__ v, const float* __restrict__ mask,
             const float* __restrict__ gate, float* __restrict__ ao)
{
    extern __shared__ float sm[];
    float* Qs   = sm;                    // [64][AST]
    float* Ks   = Qs  + 64 * AST;        // [64][AST]
    float* Ssm  = Ks  + 64 * AST;        // [64][AST]
    float* Vs   = Ssm + 64 * AST;        // [64][VST]
    float* part = Vs  + 64 * VST;        // [4][64]
    float* rsum = part + 256;            // [64]

    const int tid  = threadIdx.x;
    const int warp = tid >> 5, lane = tid & 31;
    const int g    = lane >> 2, t = lane & 3;
    const int wm   = warp >> 2;          // 0..1
    const int wn   = warp & 3;           // 0..3
    const int sb   = blockIdx.x, bh = blockIdx.y;
    const int b    = bh / HEADS, h = bh % HEADS;
    const int s0   = sb * 64;

    if (tid < 64) rsum[tid] = 0.f;

#pragma unroll
    for (int l = 0; l < 4; l++) {
        int lin = tid + l * 256, r = lin >> 4, c4 = (lin & 15) << 2;
        *(float4*)&Qs[r * AST + c4] =
            *(const float4*)&q[(size_t)(b * Ss + s0 + r) * Hh + h * KD + c4];
    }

    float oacc[2][4][4];
#pragma unroll
    for (int mi = 0; mi < 2; mi++)
#pragma unroll
        for (int nj = 0; nj < 4; nj++)
#pragma unroll
            for (int r = 0; r < 4; r++) oacc[mi][nj][r] = 0.f;

    __syncthreads();

    const size_t mbase = (size_t)h * Ss * Ss;

    for (int tt = 0; tt <= sb; tt++) {
        const int t0 = tt * 64;

#pragma unroll
        for (int l = 0; l < 4; l++) {
            int lin = tid + l * 256, r = lin >> 4, c4 = (lin & 15) << 2;
            *(float4*)&Ks[r * AST + c4] =
                *(const float4*)&k[(size_t)(b * Ss + t0 + r) * Hh + h * KD + c4];
        }
#pragma unroll
        for (int l = 0; l < 8; l++) {
            int lin = tid + l * 256, r = lin >> 5, c4 = (lin & 31) << 2;
            *(float4*)&Vs[r * VST + c4] =
                *(const float4*)&v[(size_t)(b * Ss + t0 + r) * VD + h * HD + c4];
        }
        __syncthreads();

        float sacc[2][2][4];
#pragma unroll
        for (int mi = 0; mi < 2; mi++)
#pragma unroll
            for (int nj = 0; nj < 2; nj++)
#pragma unroll
                for (int r = 0; r < 4; r++) sacc[mi][nj][r] = 0.f;

#pragma unroll
        for (int ks = 0; ks < 8; ks++) {
            const int kb = ks * 8;
            unsigned af[2][4];
#pragma unroll
            for (int mi = 0; mi < 2; mi++) {
                int mb = wm * 32 + mi * 16 + g;
                af[mi][0] = __float_as_uint(Qs[(mb    ) * AST + kb + t    ]);
                af[mi][1] = __float_as_uint(Qs[(mb + 8) * AST + kb + t    ]);
                af[mi][2] = __float_as_uint(Qs[(mb    ) * AST + kb + t + 4]);
                af[mi][3] = __float_as_uint(Qs[(mb + 8) * AST + kb + t + 4]);
            }
            unsigned bf[2][2];
#pragma unroll
            for (int nj = 0; nj < 2; nj++) {
                int nb = wn * 16 + nj * 8 + g;
                bf[nj][0] = __float_as_uint(Ks[nb * AST + kb + t    ]);
                bf[nj][1] = __float_as_uint(Ks[nb * AST + kb + t + 4]);
            }
#pragma unroll
            for (int mi = 0; mi < 2; mi++)
#pragma unroll
                for (int nj = 0; nj < 2; nj++)
                    MMA_TF32(sacc[mi][nj], af[mi], bf[nj]);
        }

        float pr[2][2] = { {0.f, 0.f}, {0.f, 0.f} };
#pragma unroll
        for (int mi = 0; mi < 2; mi++) {
            int r0 = wm * 32 + mi * 16 + g;
#pragma unroll
            for (int nj = 0; nj < 2; nj++) {
                int col = wn * 16 + nj * 8 + 2 * t;
                float2 m0 = *(const float2*)&mask[mbase + (size_t)(s0 + r0    ) * Ss + t0 + col];
                float2 m1 = *(const float2*)&mask[mbase + (size_t)(s0 + r0 + 8) * Ss + t0 + col];
                float v0 = sacc[mi][nj][0] * m0.x;
                float v1 = sacc[mi][nj][1] * m0.y;
                float v2 = sacc[mi][nj][2] * m1.x;
                float v3 = sacc[mi][nj][3] * m1.y;
                pr[mi][0] += v0 + v1;
                pr[mi][1] += v2 + v3;
                float2 s01 = { to_tf32(v0), to_tf32(v1) };
                float2 s23 = { to_tf32(v2), to_tf32(v3) };
                *(float2*)&Ssm[(r0    ) * AST + col] = s01;
                *(float2*)&Ssm[(r0 + 8) * AST + col] = s23;
            }
        }
#pragma unroll
        for (int mi = 0; mi < 2; mi++)
#pragma unroll
            for (int rr = 0; rr < 2; rr++) {
                float p = pr[mi][rr];
                p += __shfl_xor_sync(0xffffffffu, p, 1);
                p += __shfl_xor_sync(0xffffffffu, p, 2);
                if (t == 0) part[wn * 64 + wm * 32 + mi * 16 + rr * 8 + g] = p;
            }
        __syncthreads();

        if (tid < 64)
            rsum[tid] += (part[tid] + part[64 + tid]) + (part[128 + tid] + part[192 + tid]);

#pragma unroll
        for (int ks = 0; ks < 8; ks++) {
            const int kb = ks * 8;
            unsigned af[2][4];
#pragma unroll
            for (int mi = 0; mi < 2; mi++) {
                int mb = wm * 32 + mi * 16 + g;
                af[mi][0] = __float_as_uint(Ssm[(mb    ) * AST + kb + t    ]);
                af[mi][1] = __float_as_uint(Ssm[(mb + 8) * AST + kb + t    ]);
                af[mi][2] = __float_as_uint(Ssm[(mb    ) * AST + kb + t + 4]);
                af[mi][3] = __float_as_uint(Ssm[(mb + 8) * AST + kb + t + 4]);
            }
            unsigned bf[4][2];
#pragma unroll
            for (int nj = 0; nj < 4; nj++) {
                int nb = wn * 32 + nj * 8 + g;
                bf[nj][0] = __float_as_uint(Vs[(kb + t    ) * VST + nb]);
                bf[nj][1] = __float_as_uint(Vs[(kb + t + 4) * VST + nb]);
            }
#pragma unroll
            for (int mi = 0; mi < 2; mi++)
#pragma unroll
                for (int nj = 0; nj < 4; nj++)
                    MMA_TF32(oacc[mi][nj], af[mi], bf[nj]);
        }
        __syncthreads();
    }

    // ---- epilogue: rowsum divide, fused group-RMSnorm + SiLU gate ---------
    float ssq[2][2] = { {0.f, 0.f}, {0.f, 0.f} };
#pragma unroll
    for (int mi = 0; mi < 2; mi++) {
        int r0 = wm * 32 + mi * 16 + g;
        float i0 = 1.f / fmaxf(fabsf(rsum[r0    ]), 1.f);
        float i1 = 1.f / fmaxf(fabsf(rsum[r0 + 8]), 1.f);
#pragma unroll
        for (int nj = 0; nj < 4; nj++) {
            oacc[mi][nj][0] *= i0;  oacc[mi][nj][1] *= i0;
            oacc[mi][nj][2] *= i1;  oacc[mi][nj][3] *= i1;
            ssq[mi][0] += oacc[mi][nj][0] * oacc[mi][nj][0]
                        + oacc[mi][nj][1] * oacc[mi][nj][1];
            ssq[mi][1] += oacc[mi][nj][2] * oacc[mi][nj][2]
                        + oacc[mi][nj][3] * oacc[mi][nj][3];
        }
    }
#pragma unroll
    for (int mi = 0; mi < 2; mi++)
#pragma unroll
        for (int rr = 0; rr < 2; rr++) {
            float p = ssq[mi][rr];
            p += __shfl_xor_sync(0xffffffffu, p, 1);
            p += __shfl_xor_sync(0xffffffffu, p, 2);
            if (t == 0) part[wn * 64 + wm * 32 + mi * 16 + rr * 8 + g] = p;
        }
    __syncthreads();

#pragma unroll
    for (int mi = 0; mi < 2; mi++) {
        int rl = wm * 32 + mi * 16 + g;
        float t0s = part[rl    ] + part[64 + rl    ] + part[128 + rl    ] + part[192 + rl    ];
        float t1s = part[rl + 8] + part[64 + rl + 8] + part[128 + rl + 8] + part[192 + rl + 8];
        float rms0 = rsqrtf(t0s * (1.f / 128.f) + 1e-5f);
        float rms1 = rsqrtf(t1s * (1.f / 128.f) + 1e-5f);
#pragma unroll
        for (int nj = 0; nj < 4; nj++) {
            int col = h * HD + wn * 32 + nj * 8 + 2 * t;
            size_t off0 = (size_t)(b * Ss + s0 + rl    ) * VD + col;
            size_t off1 = (size_t)(b * Ss + s0 + rl + 8) * VD + col;
            float2 gv0 = *(const float2*)&gate[off0];
            float2 gv1 = *(const float2*)&gate[off1];
            float2 o0, o1;
            o0.x = to_tf32(oacc[mi][nj][0] * rms0 * gv0.x * (1.f / (1.f + __expf(-gv0.x))));
            o0.y = to_tf32(oacc[mi][nj][1] * rms0 * gv0.y * (1.f / (1.f + __expf(-gv0.y))));
            o1.x = to_tf32(oacc[mi][nj][2] * rms1 * gv1.x * (1.f / (1.f + __expf(-gv1.x))));
            o1.y = to_tf32(oacc[mi][nj][3] * rms1 * gv1.y * (1.f / (1.f + __expf(-gv1.y))));
            *(float2*)&ao[off0] = o0;
            *(float2*)&ao[off1] = o1;
        }
    }
}

// ---------------- launcher -------------------------------------------------
extern "C" void kernel_launch(void* const* d_in, const int* in_sizes, int n_in,
                              void* d_out, int out_size)
{
    const float* x    = (const float*)d_in[0];
    const float* sn   = (const float*)d_in[1];
    const float* cs   = (const float*)d_in[2];
    const float* mask = (const float*)d_in[3];
    const float* Wq   = (const float*)d_in[4];
    const float* Wk   = (const float*)d_in[5];
    const float* Wv   = (const float*)d_in[6];
    const float* Wg   = (const float*)d_in[7];
    const float* Wo   = (const float*)d_in[8];
    float* out = (float*)d_out;

    float *q, *k, *v, *g, *ao, *xr, *wr;
    cudaGetSymbolAddress((void**)&q,  g_q);
    cudaGetSymbolAddress((void**)&k,  g_k);
    cudaGetSymbolAddress((void**)&v,  g_v);
    cudaGetSymbolAddress((void**)&g,  g_g);
    cudaGetSymbolAddress((void**)&ao, g_ao);
    cudaGetSymbolAddress((void**)&xr, g_xr);
    cudaGetSymbolAddress((void**)&wr, g_wr);

    const int attn_smem = (3 * 64 * AST + 64 * VST + 256 + 64) * (int)sizeof(float);
    cudaFuncSetAttribute(attn_tc, cudaFuncAttributeMaxDynamicSharedMemorySize,
                         attn_smem);

    pre_round<<<12288, 256>>>((const float4*)x,  (const float4*)Wq,
                              (const float4*)Wk, (const float4*)Wv,
                              (const float4*)Wg, (const float4*)Wo,
                              (float4*)xr, (float4*)wr);

    proj_qkvg<<<dim3(48, 32), 128>>>(xr, wr, sn, cs, q, k, v, g);

    attn_tc<<<dim3(Ss / 64, Bb * HEADS), 256, attn_smem>>>(q, k, v, mask, g, ao);

    gemm_out<<<dim3(8, 32), 128>>>(ao, wr + 6 * 1024 * 1024, out);
}